// round 2
// baseline (speedup 1.0000x reference)
#include <cuda_runtime.h>
#include <math.h>

#define N 256
#define C 128
#define H 4
#define D 32
#define NP (N*N)            // 65536 positions
#define EPSV 1e-5f
#define INFV 1000000000.0f

// Scratch (static device arrays; no allocation in kernel_launch)
__device__ float g_xn[NP*C];        // layernormed x           32 MB
__device__ float g_tri[H*N*N];      // tri bias, transposed [h][k][q]  1 MB
__device__ float g_proj[4][NP*C];   // q, k, v, gate-logits   134 MB
__device__ float g_o[NP*C];         // attention output        32 MB

// ---------------------------------------------------------------------------
// Kernel 1: LayerNorm over C + triangle-bias projection (stored transposed)
// One warp per (i,j) position. 8 warps / block.
// ---------------------------------------------------------------------------
__global__ void k_ln_tri(const float* __restrict__ x,
                         const float* __restrict__ ln_w,
                         const float* __restrict__ ln_b,
                         const float* __restrict__ w_tri) {
    __shared__ float swt[H*C];
    int tid = threadIdx.x;
    swt[tid]       = w_tri[tid];
    swt[tid + 256] = w_tri[tid + 256];
    __syncthreads();

    int warp = tid >> 5, lane = tid & 31;
    int pos = (blockIdx.x << 3) + warp;

    const float4 a = ((const float4*)(x + (size_t)pos * C))[lane];
    float s  = a.x + a.y + a.z + a.w;
    float s2 = a.x*a.x + a.y*a.y + a.z*a.z + a.w*a.w;
#pragma unroll
    for (int o = 16; o > 0; o >>= 1) {
        s  += __shfl_xor_sync(0xffffffffu, s,  o);
        s2 += __shfl_xor_sync(0xffffffffu, s2, o);
    }
    float mu   = s * (1.0f / C);
    float var  = s2 * (1.0f / C) - mu * mu;
    float rstd = rsqrtf(var + EPSV);

    float4 w = ((const float4*)ln_w)[lane];
    float4 b = ((const float4*)ln_b)[lane];
    float4 xn;
    xn.x = (a.x - mu) * rstd * w.x + b.x;
    xn.y = (a.y - mu) * rstd * w.y + b.y;
    xn.z = (a.z - mu) * rstd * w.z + b.z;
    xn.w = (a.w - mu) * rstd * w.w + b.w;
    ((float4*)(g_xn + (size_t)pos * C))[lane] = xn;

    // tri[h, q=row, k=col] = xn . w_tri[h]
    float t[H];
#pragma unroll
    for (int h = 0; h < H; ++h) {
        const float4 wt = ((const float4*)(swt + h * C))[lane];
        t[h] = xn.x*wt.x + xn.y*wt.y + xn.z*wt.z + xn.w*wt.w;
    }
#pragma unroll
    for (int h = 0; h < H; ++h)
#pragma unroll
        for (int o = 16; o > 0; o >>= 1)
            t[h] += __shfl_xor_sync(0xffffffffu, t[h], o);

    if (lane == 0) {
        int r = pos >> 8, cidx = pos & 255;
        // transposed store: tri_t[h][k=cidx][q=r]
#pragma unroll
        for (int h = 0; h < H; ++h)
            g_tri[(h * N + cidx) * N + r] = t[h];
    }
}

// ---------------------------------------------------------------------------
// Kernel 2: QKV + gate projections.  g_proj[sel][pos][e] = xn[pos,:] . W[e,:]
// Tiled GEMM: 64 rows x 64 cols per block, K in two 64-chunks.
// grid = (NP/64, 8): blockIdx.y -> (weight sel, col half)
// ---------------------------------------------------------------------------
__global__ void k_proj(const float* __restrict__ wq, const float* __restrict__ wk,
                       const float* __restrict__ wv, const float* __restrict__ wg) {
    __shared__ float As[64][65];   // [k][m]
    __shared__ float Bs[64][65];   // [k][n]
    int tid = threadIdx.x;
    int wsel = blockIdx.y >> 1;
    int n0 = (blockIdx.y & 1) * 64;
    const float* W = (wsel == 0) ? wq : (wsel == 1) ? wk : (wsel == 2) ? wv : wg;
    float* Out = g_proj[wsel];
    int m0 = blockIdx.x * 64;
    int tx = tid & 15, ty = tid >> 4;
    float acc[4][4] = {};

    for (int kc = 0; kc < C; kc += 64) {
#pragma unroll
        for (int i = 0; i < 16; ++i) {
            int idx = tid + i * 256;           // 0..4095
            int row = idx >> 6, kk = idx & 63;
            As[kk][row] = g_xn[(size_t)(m0 + row) * C + kc + kk];
            Bs[kk][row] = W[(size_t)(n0 + row) * C + kc + kk];
        }
        __syncthreads();
#pragma unroll 16
        for (int k = 0; k < 64; ++k) {
            float a0 = As[k][ty*4+0], a1 = As[k][ty*4+1], a2 = As[k][ty*4+2], a3 = As[k][ty*4+3];
            float b0 = Bs[k][tx*4+0], b1 = Bs[k][tx*4+1], b2 = Bs[k][tx*4+2], b3 = Bs[k][tx*4+3];
            acc[0][0] += a0*b0; acc[0][1] += a0*b1; acc[0][2] += a0*b2; acc[0][3] += a0*b3;
            acc[1][0] += a1*b0; acc[1][1] += a1*b1; acc[1][2] += a1*b2; acc[1][3] += a1*b3;
            acc[2][0] += a2*b0; acc[2][1] += a2*b1; acc[2][2] += a2*b2; acc[2][3] += a2*b3;
            acc[3][0] += a3*b0; acc[3][1] += a3*b1; acc[3][2] += a3*b2; acc[3][3] += a3*b3;
        }
        __syncthreads();
    }
#pragma unroll
    for (int r = 0; r < 4; ++r)
#pragma unroll
        for (int c = 0; c < 4; ++c)
            Out[(size_t)(m0 + ty*4 + r) * C + n0 + tx*4 + c] = acc[r][c];
}

// ---------------------------------------------------------------------------
// Kernel 3: attention. One block per (row i, head h). One thread per query.
// K,V processed in two 128-key tiles held in STATIC smem (33 KB total),
// online softmax state carried across tiles. No dynamic smem, no attribute.
// ---------------------------------------------------------------------------
#define TK 128   // keys per tile

__global__ void k_attn(const float* __restrict__ mask) {
    __shared__ float Ks[TK * D];   // 16 KB
    __shared__ float Vs[TK * D];   // 16 KB
    __shared__ float mb[N];        // 1 KB

    int i = blockIdx.x, h = blockIdx.y;
    int tid = threadIdx.x;     // query position

    mb[tid] = INFV * (mask[i * N + tid] - 1.0f);

    float q[D];
    const float* Qg = g_proj[0] + ((size_t)i * N + tid) * C + h * D;
#pragma unroll
    for (int d = 0; d < D; ++d) q[d] = Qg[d] * 0.17677669529663688f;  // 1/sqrt(32)

    float m = -3.4e38f, l = 0.0f;
    float o[D];
#pragma unroll
    for (int d = 0; d < D; ++d) o[d] = 0.0f;

    const float* trirow = g_tri + (size_t)h * N * N + tid;  // tri_t[h][k][q=tid]
    const float* Kg = g_proj[1] + (size_t)i * N * C + h * D;
    const float* Vg = g_proj[2] + (size_t)i * N * C + h * D;

    for (int t0 = 0; t0 < N; t0 += TK) {
        __syncthreads();
        // load this tile: TK*D floats = TK*8 float4 = 1024 float4, 256 threads
#pragma unroll
        for (int j = 0; j < (TK * D / 4) / 256; ++j) {
            int idx = tid + j * 256;
            int kpos = idx >> 3, d4 = idx & 7;
            ((float4*)Ks)[idx] = ((const float4*)(Kg + (size_t)(t0 + kpos) * C))[d4];
            ((float4*)Vs)[idx] = ((const float4*)(Vg + (size_t)(t0 + kpos) * C))[d4];
        }
        __syncthreads();

        for (int kk = 0; kk < TK; ++kk) {
            int kpos = t0 + kk;
            const float* kr = Ks + kk * D;
            float s = 0.0f;
#pragma unroll
            for (int d = 0; d < D; ++d) s += q[d] * kr[d];
            s += trirow[(size_t)kpos * N] + mb[kpos];

            if (s > m) {
                float scale = __expf(m - s);
                l *= scale;
#pragma unroll
                for (int d = 0; d < D; ++d) o[d] *= scale;
                m = s;
            }
            float p = __expf(s - m);
            l += p;
            const float* vr = Vs + kk * D;
#pragma unroll
            for (int d = 0; d < D; ++d) o[d] += p * vr[d];
        }
    }

    float inv = 1.0f / l;
    float* Og = g_o + ((size_t)i * N + tid) * C + h * D;
#pragma unroll
    for (int d = 0; d < D; ++d) Og[d] = o[d] * inv;
}

// ---------------------------------------------------------------------------
// Kernel 4: gated output projection.
// out[pos,c] = sum_e (o[pos,e] * sigmoid(gp[pos,e]+bg[e])) * wo[c,e] + bo[c]
// ---------------------------------------------------------------------------
__global__ void k_out(const float* __restrict__ wo, const float* __restrict__ bg,
                      const float* __restrict__ bo, float* __restrict__ out) {
    __shared__ float As[64][65];
    __shared__ float Bs[64][65];
    int tid = threadIdx.x;
    int m0 = blockIdx.x * 64;
    int n0 = blockIdx.y * 64;
    int tx = tid & 15, ty = tid >> 4;
    float acc[4][4] = {};

    for (int kc = 0; kc < C; kc += 64) {
#pragma unroll
        for (int i = 0; i < 16; ++i) {
            int idx = tid + i * 256;
            int row = idx >> 6, kk = idx & 63;
            int e = kc + kk;
            size_t ai = (size_t)(m0 + row) * C + e;
            float gv = 1.0f / (1.0f + __expf(-(g_proj[3][ai] + bg[e])));
            As[kk][row] = g_o[ai] * gv;
            Bs[kk][row] = wo[(size_t)(n0 + row) * C + e];
        }
        __syncthreads();
#pragma unroll 16
        for (int k = 0; k < 64; ++k) {
            float a0 = As[k][ty*4+0], a1 = As[k][ty*4+1], a2 = As[k][ty*4+2], a3 = As[k][ty*4+3];
            float b0 = Bs[k][tx*4+0], b1 = Bs[k][tx*4+1], b2 = Bs[k][tx*4+2], b3 = Bs[k][tx*4+3];
            acc[0][0] += a0*b0; acc[0][1] += a0*b1; acc[0][2] += a0*b2; acc[0][3] += a0*b3;
            acc[1][0] += a1*b0; acc[1][1] += a1*b1; acc[1][2] += a1*b2; acc[1][3] += a1*b3;
            acc[2][0] += a2*b0; acc[2][1] += a2*b1; acc[2][2] += a2*b2; acc[2][3] += a2*b3;
            acc[3][0] += a3*b0; acc[3][1] += a3*b1; acc[3][2] += a3*b2; acc[3][3] += a3*b3;
        }
        __syncthreads();
    }
#pragma unroll
    for (int r = 0; r < 4; ++r)
#pragma unroll
        for (int c = 0; c < 4; ++c)
            out[(size_t)(m0 + ty*4 + r) * C + n0 + tx*4 + c] = acc[r][c] + bo[n0 + tx*4 + c];
}

// ---------------------------------------------------------------------------
extern "C" void kernel_launch(void* const* d_in, const int* in_sizes, int n_in,
                              void* d_out, int out_size) {
    const float* x     = (const float*)d_in[0];
    const float* mask  = (const float*)d_in[1];
    const float* ln_w  = (const float*)d_in[2];
    const float* ln_b  = (const float*)d_in[3];
    const float* w_tri = (const float*)d_in[4];
    const float* wq    = (const float*)d_in[5];
    const float* wk    = (const float*)d_in[6];
    const float* wv    = (const float*)d_in[7];
    const float* wg    = (const float*)d_in[8];
    const float* bg    = (const float*)d_in[9];
    const float* wo    = (const float*)d_in[10];
    const float* bo    = (const float*)d_in[11];
    float* out = (float*)d_out;

    (void)in_sizes; (void)n_in; (void)out_size;

    k_ln_tri<<<NP / 8, 256>>>(x, ln_w, ln_b, w_tri);
    k_proj<<<dim3(NP / 64, 8), 256>>>(wq, wk, wv, wg);
    k_attn<<<dim3(N, H), 256>>>(mask);
    k_out<<<dim3(NP / 64, 2), 256>>>(wo, bg, bo, out);
}

// round 3
// speedup vs baseline: 1.2867x; 1.2867x over previous
#include <cuda_runtime.h>
#include <math.h>

#define N 256
#define C 128
#define H 4
#define D 32
#define NP (N*N)            // 65536 positions
#define EPSV 1e-5f
#define INFV 1000000000.0f
#define PAD 132             // smem row pitch (floats): 16B-aligned rows

// Scratch (static device arrays; no allocation in kernel_launch)
__device__ float g_xn[NP*C];        // layernormed x           32 MB
__device__ float g_tri[H*N*N];      // tri bias, transposed [h][k][q]  1 MB
__device__ float g_proj[4][NP*C];   // q, k, v, gate-logits   134 MB
__device__ float g_o[NP*C];         // attention output        32 MB

// ---------------------------------------------------------------------------
// Kernel 1: LayerNorm over C + triangle-bias projection (stored transposed)
// One warp per (i,j) position. 8 warps / block.
// ---------------------------------------------------------------------------
__global__ void k_ln_tri(const float* __restrict__ x,
                         const float* __restrict__ ln_w,
                         const float* __restrict__ ln_b,
                         const float* __restrict__ w_tri) {
    __shared__ float swt[H*C];
    int tid = threadIdx.x;
    swt[tid]       = w_tri[tid];
    swt[tid + 256] = w_tri[tid + 256];
    __syncthreads();

    int warp = tid >> 5, lane = tid & 31;
    int pos = (blockIdx.x << 3) + warp;

    const float4 a = ((const float4*)(x + (size_t)pos * C))[lane];
    float s  = a.x + a.y + a.z + a.w;
    float s2 = a.x*a.x + a.y*a.y + a.z*a.z + a.w*a.w;
#pragma unroll
    for (int o = 16; o > 0; o >>= 1) {
        s  += __shfl_xor_sync(0xffffffffu, s,  o);
        s2 += __shfl_xor_sync(0xffffffffu, s2, o);
    }
    float mu   = s * (1.0f / C);
    float var  = s2 * (1.0f / C) - mu * mu;
    float rstd = rsqrtf(var + EPSV);

    float4 w = ((const float4*)ln_w)[lane];
    float4 b = ((const float4*)ln_b)[lane];
    float4 xn;
    xn.x = (a.x - mu) * rstd * w.x + b.x;
    xn.y = (a.y - mu) * rstd * w.y + b.y;
    xn.z = (a.z - mu) * rstd * w.z + b.z;
    xn.w = (a.w - mu) * rstd * w.w + b.w;
    ((float4*)(g_xn + (size_t)pos * C))[lane] = xn;

    float t[H];
#pragma unroll
    for (int h = 0; h < H; ++h) {
        const float4 wt = ((const float4*)(swt + h * C))[lane];
        t[h] = xn.x*wt.x + xn.y*wt.y + xn.z*wt.z + xn.w*wt.w;
    }
#pragma unroll
    for (int h = 0; h < H; ++h)
#pragma unroll
        for (int o = 16; o > 0; o >>= 1)
            t[h] += __shfl_xor_sync(0xffffffffu, t[h], o);

    if (lane == 0) {
        int r = pos >> 8, cidx = pos & 255;
#pragma unroll
        for (int h = 0; h < H; ++h)
            g_tri[(h * N + cidx) * N + r] = t[h];   // tri_t[h][k][q]
    }
}

// ---------------------------------------------------------------------------
// Kernel 2: QKV + gate projections. 128x128 tile, 8x8 per-thread blocking.
// grid = (NP/128, 4). blockIdx.y selects weight / output buffer.
// A[m][k] = g_xn (m=position, k=channel), B[n][k] = W (n=out dim).
// ---------------------------------------------------------------------------
__global__ void __launch_bounds__(256)
k_proj(const float* __restrict__ wq, const float* __restrict__ wk,
       const float* __restrict__ wv, const float* __restrict__ wg) {
    __shared__ float As[16][PAD];
    __shared__ float Bs[16][PAD];
    int tid = threadIdx.x;
    int wsel = blockIdx.y;
    const float* W = (wsel == 0) ? wq : (wsel == 1) ? wk : (wsel == 2) ? wv : wg;
    float* Out = g_proj[wsel];
    int m0 = blockIdx.x * 128;
    int tx = tid & 15, ty = tid >> 4;
    float acc[8][8] = {};

    for (int kc = 0; kc < C; kc += 16) {
        __syncthreads();
#pragma unroll
        for (int i = 0; i < 2; ++i) {
            int idx = tid + i * 256;       // 0..511
            int row = idx >> 2, k4 = idx & 3;
            float4 a = *(const float4*)&g_xn[(size_t)(m0 + row) * C + kc + k4 * 4];
            As[k4*4+0][row] = a.x; As[k4*4+1][row] = a.y;
            As[k4*4+2][row] = a.z; As[k4*4+3][row] = a.w;
            float4 b = *(const float4*)&W[(size_t)row * C + kc + k4 * 4];
            Bs[k4*4+0][row] = b.x; Bs[k4*4+1][row] = b.y;
            Bs[k4*4+2][row] = b.z; Bs[k4*4+3][row] = b.w;
        }
        __syncthreads();
#pragma unroll
        for (int kk = 0; kk < 16; ++kk) {
            float4 a0 = *(const float4*)&As[kk][ty * 4];
            float4 a1 = *(const float4*)&As[kk][64 + ty * 4];
            float4 b0 = *(const float4*)&Bs[kk][tx * 4];
            float4 b1 = *(const float4*)&Bs[kk][64 + tx * 4];
            float av[8] = {a0.x,a0.y,a0.z,a0.w,a1.x,a1.y,a1.z,a1.w};
            float bv[8] = {b0.x,b0.y,b0.z,b0.w,b1.x,b1.y,b1.z,b1.w};
#pragma unroll
            for (int r = 0; r < 8; ++r)
#pragma unroll
                for (int c = 0; c < 8; ++c)
                    acc[r][c] += av[r] * bv[c];
        }
    }
#pragma unroll
    for (int r = 0; r < 8; ++r) {
        int m = m0 + ((r < 4) ? (ty * 4 + r) : (64 + ty * 4 + r - 4));
        float4 v0 = {acc[r][0], acc[r][1], acc[r][2], acc[r][3]};
        float4 v1 = {acc[r][4], acc[r][5], acc[r][6], acc[r][7]};
        *(float4*)&Out[(size_t)m * C + tx * 4]      = v0;
        *(float4*)&Out[(size_t)m * C + 64 + tx * 4] = v1;
    }
}

// ---------------------------------------------------------------------------
// Kernel 3: attention. One block per (row i, head h). One thread per query.
// Two 128-key tiles in static smem, online softmax carried across tiles.
// ---------------------------------------------------------------------------
#define TK 128   // keys per tile

__global__ void k_attn(const float* __restrict__ mask) {
    __shared__ float Ks[TK * D];   // 16 KB
    __shared__ float Vs[TK * D];   // 16 KB
    __shared__ float mb[N];        // 1 KB

    int i = blockIdx.x, h = blockIdx.y;
    int tid = threadIdx.x;     // query position

    mb[tid] = INFV * (mask[i * N + tid] - 1.0f);

    float q[D];
    const float* Qg = g_proj[0] + ((size_t)i * N + tid) * C + h * D;
#pragma unroll
    for (int d = 0; d < D; ++d) q[d] = Qg[d] * 0.17677669529663688f;  // 1/sqrt(32)

    float m = -3.4e38f, l = 0.0f;
    float o[D];
#pragma unroll
    for (int d = 0; d < D; ++d) o[d] = 0.0f;

    const float* trirow = g_tri + (size_t)h * N * N + tid;  // tri_t[h][k][q=tid]
    const float* Kg = g_proj[1] + (size_t)i * N * C + h * D;
    const float* Vg = g_proj[2] + (size_t)i * N * C + h * D;

    for (int t0 = 0; t0 < N; t0 += TK) {
        __syncthreads();
#pragma unroll
        for (int j = 0; j < (TK * D / 4) / 256; ++j) {
            int idx = tid + j * 256;
            int kpos = idx >> 3, d4 = idx & 7;
            ((float4*)Ks)[idx] = ((const float4*)(Kg + (size_t)(t0 + kpos) * C))[d4];
            ((float4*)Vs)[idx] = ((const float4*)(Vg + (size_t)(t0 + kpos) * C))[d4];
        }
        __syncthreads();

        for (int kk = 0; kk < TK; ++kk) {
            int kpos = t0 + kk;
            const float* kr = Ks + kk * D;
            float s = 0.0f;
#pragma unroll
            for (int d = 0; d < D; ++d) s += q[d] * kr[d];
            s += trirow[(size_t)kpos * N] + mb[kpos];

            if (s > m) {
                float scale = __expf(m - s);
                l *= scale;
#pragma unroll
                for (int d = 0; d < D; ++d) o[d] *= scale;
                m = s;
            }
            float p = __expf(s - m);
            l += p;
            const float* vr = Vs + kk * D;
#pragma unroll
            for (int d = 0; d < D; ++d) o[d] += p * vr[d];
        }
    }

    float inv = 1.0f / l;
    float* Og = g_o + ((size_t)i * N + tid) * C + h * D;
#pragma unroll
    for (int d = 0; d < D; ++d) Og[d] = o[d] * inv;
}

// ---------------------------------------------------------------------------
// Kernel 4: gated output projection. Same 128x128 / 8x8 GEMM skeleton.
// A[m][e] = g_o * sigmoid(gate_logit + bg), B[c][e] = wo. out += bo.
// grid = (NP/128).
// ---------------------------------------------------------------------------
__global__ void __launch_bounds__(256)
k_out(const float* __restrict__ wo, const float* __restrict__ bg,
      const float* __restrict__ bo, float* __restrict__ out) {
    __shared__ float As[16][PAD];
    __shared__ float Bs[16][PAD];
    int tid = threadIdx.x;
    int m0 = blockIdx.x * 128;
    int tx = tid & 15, ty = tid >> 4;
    float acc[8][8] = {};

    for (int kc = 0; kc < C; kc += 16) {
        __syncthreads();
#pragma unroll
        for (int i = 0; i < 2; ++i) {
            int idx = tid + i * 256;
            int row = idx >> 2, k4 = idx & 3;
            size_t ai = (size_t)(m0 + row) * C + kc + k4 * 4;
            float4 ov = *(const float4*)&g_o[ai];
            float4 gp = *(const float4*)&g_proj[3][ai];
            float4 bgv = *(const float4*)&bg[kc + k4 * 4];
            As[k4*4+0][row] = ov.x / (1.0f + __expf(-(gp.x + bgv.x)));
            As[k4*4+1][row] = ov.y / (1.0f + __expf(-(gp.y + bgv.y)));
            As[k4*4+2][row] = ov.z / (1.0f + __expf(-(gp.z + bgv.z)));
            As[k4*4+3][row] = ov.w / (1.0f + __expf(-(gp.w + bgv.w)));
            float4 b = *(const float4*)&wo[(size_t)row * C + kc + k4 * 4];
            Bs[k4*4+0][row] = b.x; Bs[k4*4+1][row] = b.y;
            Bs[k4*4+2][row] = b.z; Bs[k4*4+3][row] = b.w;
        }
        __syncthreads();
#pragma unroll
        for (int kk = 0; kk < 16; ++kk) {
            float4 a0 = *(const float4*)&As[kk][ty * 4];
            float4 a1 = *(const float4*)&As[kk][64 + ty * 4];
            float4 b0 = *(const float4*)&Bs[kk][tx * 4];
            float4 b1 = *(const float4*)&Bs[kk][64 + tx * 4];
            float av[8] = {a0.x,a0.y,a0.z,a0.w,a1.x,a1.y,a1.z,a1.w};
            float bv[8] = {b0.x,b0.y,b0.z,b0.w,b1.x,b1.y,b1.z,b1.w};
#pragma unroll
            for (int r = 0; r < 8; ++r)
#pragma unroll
                for (int c = 0; c < 8; ++c)
                    acc[r][c] += av[r] * bv[c];
        }
    }
    float4 bo0 = *(const float4*)&bo[tx * 4];
    float4 bo1 = *(const float4*)&bo[64 + tx * 4];
#pragma unroll
    for (int r = 0; r < 8; ++r) {
        int m = m0 + ((r < 4) ? (ty * 4 + r) : (64 + ty * 4 + r - 4));
        float4 v0 = {acc[r][0] + bo0.x, acc[r][1] + bo0.y, acc[r][2] + bo0.z, acc[r][3] + bo0.w};
        float4 v1 = {acc[r][4] + bo1.x, acc[r][5] + bo1.y, acc[r][6] + bo1.z, acc[r][7] + bo1.w};
        *(float4*)&out[(size_t)m * C + tx * 4]      = v0;
        *(float4*)&out[(size_t)m * C + 64 + tx * 4] = v1;
    }
}

// ---------------------------------------------------------------------------
extern "C" void kernel_launch(void* const* d_in, const int* in_sizes, int n_in,
                              void* d_out, int out_size) {
    const float* x     = (const float*)d_in[0];
    const float* mask  = (const float*)d_in[1];
    const float* ln_w  = (const float*)d_in[2];
    const float* ln_b  = (const float*)d_in[3];
    const float* w_tri = (const float*)d_in[4];
    const float* wq    = (const float*)d_in[5];
    const float* wk    = (const float*)d_in[6];
    const float* wv    = (const float*)d_in[7];
    const float* wg    = (const float*)d_in[8];
    const float* bg    = (const float*)d_in[9];
    const float* wo    = (const float*)d_in[10];
    const float* bo    = (const float*)d_in[11];
    float* out = (float*)d_out;

    (void)in_sizes; (void)n_in; (void)out_size;

    k_ln_tri<<<NP / 8, 256>>>(x, ln_w, ln_b, w_tri);
    k_proj<<<dim3(NP / 128, 4), 256>>>(wq, wk, wv, wg);
    k_attn<<<dim3(N, H), 256>>>(mask);
    k_out<<<NP / 128, 256>>>(wo, bg, bo, out);
}

// round 5
// speedup vs baseline: 1.5288x; 1.1882x over previous
#include <cuda_runtime.h>
#include <math.h>
#include <stdint.h>

#define N 256
#define C 128
#define H 4
#define D 32
#define NP (N*N)            // 65536 positions
#define EPSV 1e-5f
#define INFV 1000000000.0f
#define KP 20               // smem row pitch for 16-wide k-chunk (conflict-free)

// Scratch (static device arrays; no allocation in kernel_launch)
__device__ float g_xn[NP*C];        // layernormed x           32 MB
__device__ float g_tri[H*N*N];      // tri bias, transposed [h][k][q]  1 MB
__device__ float g_proj[4][NP*C];   // q, k, v, gate-logits   134 MB
__device__ float g_o[NP*C];         // attention output        32 MB

__device__ __forceinline__ uint32_t f2tf32(float f) {
    uint32_t u;
    asm("cvt.rna.tf32.f32 %0, %1;" : "=r"(u) : "f"(f));
    return u;
}

__device__ __forceinline__ void mma_tf32(float& d0, float& d1, float& d2, float& d3,
                                         uint32_t a0, uint32_t a1, uint32_t a2, uint32_t a3,
                                         uint32_t b0, uint32_t b1) {
    asm volatile(
        "mma.sync.aligned.m16n8k8.row.col.f32.tf32.tf32.f32 "
        "{%0,%1,%2,%3}, {%4,%5,%6,%7}, {%8,%9}, {%0,%1,%2,%3};\n"
        : "+f"(d0), "+f"(d1), "+f"(d2), "+f"(d3)
        : "r"(a0), "r"(a1), "r"(a2), "r"(a3), "r"(b0), "r"(b1));
}

// ---------------------------------------------------------------------------
// Kernel 1: LayerNorm over C + triangle-bias projection (stored transposed)
// ---------------------------------------------------------------------------
__global__ void k_ln_tri(const float* __restrict__ x,
                         const float* __restrict__ ln_w,
                         const float* __restrict__ ln_b,
                         const float* __restrict__ w_tri) {
    __shared__ float swt[H*C];
    int tid = threadIdx.x;
    swt[tid]       = w_tri[tid];
    swt[tid + 256] = w_tri[tid + 256];
    __syncthreads();

    int warp = tid >> 5, lane = tid & 31;
    int pos = (blockIdx.x << 3) + warp;

    const float4 a = ((const float4*)(x + (size_t)pos * C))[lane];
    float s  = a.x + a.y + a.z + a.w;
    float s2 = a.x*a.x + a.y*a.y + a.z*a.z + a.w*a.w;
#pragma unroll
    for (int o = 16; o > 0; o >>= 1) {
        s  += __shfl_xor_sync(0xffffffffu, s,  o);
        s2 += __shfl_xor_sync(0xffffffffu, s2, o);
    }
    float mu   = s * (1.0f / C);
    float var  = s2 * (1.0f / C) - mu * mu;
    float rstd = rsqrtf(var + EPSV);

    float4 w = ((const float4*)ln_w)[lane];
    float4 b = ((const float4*)ln_b)[lane];
    float4 xn;
    xn.x = (a.x - mu) * rstd * w.x + b.x;
    xn.y = (a.y - mu) * rstd * w.y + b.y;
    xn.z = (a.z - mu) * rstd * w.z + b.z;
    xn.w = (a.w - mu) * rstd * w.w + b.w;
    ((float4*)(g_xn + (size_t)pos * C))[lane] = xn;

    float t[H];
#pragma unroll
    for (int h = 0; h < H; ++h) {
        const float4 wt = ((const float4*)(swt + h * C))[lane];
        t[h] = xn.x*wt.x + xn.y*wt.y + xn.z*wt.z + xn.w*wt.w;
    }
#pragma unroll
    for (int h = 0; h < H; ++h)
#pragma unroll
        for (int o = 16; o > 0; o >>= 1)
            t[h] += __shfl_xor_sync(0xffffffffu, t[h], o);

    if (lane == 0) {
        int r = pos >> 8, cidx = pos & 255;
#pragma unroll
        for (int h = 0; h < H; ++h)
            g_tri[(h * N + cidx) * N + r] = t[h];   // tri_t[h][k][q]
    }
}

// ---------------------------------------------------------------------------
// tf32 MMA GEMM core: block tile 128(M)x128(N), K staged 16 at a time.
// 8 warps: wm = w>>1 (4 along M), wn = w&1 (2 along N). Warp tile 32x64.
// A[m][k] row-major in smem [row][k] pitch KP; B[n][k] same.
// ---------------------------------------------------------------------------
struct MmaAcc { float d[2][8][4]; };   // [mt][nt][reg]

__device__ __forceinline__ void mma_chunk(const float (*As)[KP], const float (*Bs)[KP],
                                          int wm, int wn, int g, int tq, MmaAcc& A) {
#pragma unroll
    for (int ks = 0; ks < 16; ks += 8) {
        uint32_t af[2][4];
#pragma unroll
        for (int mt = 0; mt < 2; ++mt) {
            int r = wm * 32 + mt * 16;
            af[mt][0] = f2tf32(As[r + g][ks + tq]);
            af[mt][1] = f2tf32(As[r + g + 8][ks + tq]);
            af[mt][2] = f2tf32(As[r + g][ks + tq + 4]);
            af[mt][3] = f2tf32(As[r + g + 8][ks + tq + 4]);
        }
        uint32_t bf[8][2];
#pragma unroll
        for (int nt = 0; nt < 8; ++nt) {
            int cb = wn * 64 + nt * 8;
            bf[nt][0] = f2tf32(Bs[cb + g][ks + tq]);
            bf[nt][1] = f2tf32(Bs[cb + g][ks + tq + 4]);
        }
#pragma unroll
        for (int mt = 0; mt < 2; ++mt)
#pragma unroll
            for (int nt = 0; nt < 8; ++nt)
                mma_tf32(A.d[mt][nt][0], A.d[mt][nt][1], A.d[mt][nt][2], A.d[mt][nt][3],
                         af[mt][0], af[mt][1], af[mt][2], af[mt][3],
                         bf[nt][0], bf[nt][1]);
    }
}

// ---------------------------------------------------------------------------
// Kernel 2: QKV + gate projections via tf32 mma. grid=(NP/128, 4).
// ---------------------------------------------------------------------------
__global__ void __launch_bounds__(256)
k_proj(const float* __restrict__ wq, const float* __restrict__ wk,
       const float* __restrict__ wv, const float* __restrict__ wg) {
    __shared__ float As[128][KP];
    __shared__ float Bs[128][KP];
    int tid = threadIdx.x;
    int wsel = blockIdx.y;
    const float* W = (wsel == 0) ? wq : (wsel == 1) ? wk : (wsel == 2) ? wv : wg;
    float* Out = g_proj[wsel];
    int m0 = blockIdx.x * 128;
    int w = tid >> 5, lane = tid & 31;
    int wm = w >> 1, wn = w & 1;
    int g = lane >> 2, tq = lane & 3;

    MmaAcc acc;
#pragma unroll
    for (int mt = 0; mt < 2; ++mt)
#pragma unroll
        for (int nt = 0; nt < 8; ++nt)
#pragma unroll
            for (int r = 0; r < 4; ++r) acc.d[mt][nt][r] = 0.0f;

    for (int kc = 0; kc < C; kc += 16) {
        __syncthreads();
#pragma unroll
        for (int i = 0; i < 2; ++i) {
            int idx = tid + i * 256;            // 0..511
            int row = idx >> 2, k4 = idx & 3;
            float4 a = *(const float4*)&g_xn[(size_t)(m0 + row) * C + kc + k4 * 4];
            *(float4*)&As[row][k4 * 4] = a;
            float4 b = *(const float4*)&W[(size_t)row * C + kc + k4 * 4];
            *(float4*)&Bs[row][k4 * 4] = b;
        }
        __syncthreads();
        mma_chunk(As, Bs, wm, wn, g, tq, acc);
    }

#pragma unroll
    for (int mt = 0; mt < 2; ++mt) {
        int r0 = m0 + wm * 32 + mt * 16 + g;
#pragma unroll
        for (int nt = 0; nt < 8; ++nt) {
            int cb = wn * 64 + nt * 8 + 2 * tq;
            *(float2*)&Out[(size_t)r0 * C + cb]       = make_float2(acc.d[mt][nt][0], acc.d[mt][nt][1]);
            *(float2*)&Out[(size_t)(r0 + 8) * C + cb] = make_float2(acc.d[mt][nt][2], acc.d[mt][nt][3]);
        }
    }
}

// ---------------------------------------------------------------------------
// Kernel 3: attention. One block per (row i, head h). One thread per query.
// ---------------------------------------------------------------------------
#define TK 128   // keys per tile

__global__ void k_attn(const float* __restrict__ mask) {
    __shared__ float Ks[TK * D];   // 16 KB
    __shared__ float Vs[TK * D];   // 16 KB
    __shared__ float mb[N];        // 1 KB

    int i = blockIdx.x, h = blockIdx.y;
    int tid = threadIdx.x;     // query position

    mb[tid] = INFV * (mask[i * N + tid] - 1.0f);

    float q[D];
    const float* Qg = g_proj[0] + ((size_t)i * N + tid) * C + h * D;
#pragma unroll
    for (int d = 0; d < D; ++d) q[d] = Qg[d] * 0.17677669529663688f;  // 1/sqrt(32)

    float m = -3.4e38f, l = 0.0f;
    float o[D];
#pragma unroll
    for (int d = 0; d < D; ++d) o[d] = 0.0f;

    const float* trirow = g_tri + (size_t)h * N * N + tid;  // tri_t[h][k][q=tid]
    const float* Kg = g_proj[1] + (size_t)i * N * C + h * D;
    const float* Vg = g_proj[2] + (size_t)i * N * C + h * D;

    for (int t0 = 0; t0 < N; t0 += TK) {
        __syncthreads();
#pragma unroll
        for (int j = 0; j < (TK * D / 4) / 256; ++j) {
            int idx = tid + j * 256;
            int kpos = idx >> 3, d4 = idx & 7;
            ((float4*)Ks)[idx] = ((const float4*)(Kg + (size_t)(t0 + kpos) * C))[d4];
            ((float4*)Vs)[idx] = ((const float4*)(Vg + (size_t)(t0 + kpos) * C))[d4];
        }
        __syncthreads();

        for (int kk = 0; kk < TK; ++kk) {
            int kpos = t0 + kk;
            const float* kr = Ks + kk * D;
            float s = 0.0f;
#pragma unroll
            for (int d = 0; d < D; ++d) s += q[d] * kr[d];
            s += trirow[(size_t)kpos * N] + mb[kpos];

            if (s > m) {
                float scale = __expf(m - s);
                l *= scale;
#pragma unroll
                for (int d = 0; d < D; ++d) o[d] *= scale;
                m = s;
            }
            float p = __expf(s - m);
            l += p;
            const float* vr = Vs + kk * D;
#pragma unroll
            for (int d = 0; d < D; ++d) o[d] += p * vr[d];
        }
    }

    float inv = 1.0f / l;
    float* Og = g_o + ((size_t)i * N + tid) * C + h * D;
#pragma unroll
    for (int d = 0; d < D; ++d) Og[d] = o[d] * inv;
}

// ---------------------------------------------------------------------------
// Kernel 4: gated output projection via tf32 mma. grid=(NP/128).
// A[m][e] = g_o * sigmoid(gate_logit + bg), B[c][e] = wo. out += bo.
// ---------------------------------------------------------------------------
__global__ void __launch_bounds__(256)
k_out(const float* __restrict__ wo, const float* __restrict__ bg,
      const float* __restrict__ bo, float* __restrict__ out) {
    __shared__ float As[128][KP];
    __shared__ float Bs[128][KP];
    int tid = threadIdx.x;
    int m0 = blockIdx.x * 128;
    int w = tid >> 5, lane = tid & 31;
    int wm = w >> 1, wn = w & 1;
    int g = lane >> 2, tq = lane & 3;

    MmaAcc acc;
#pragma unroll
    for (int mt = 0; mt < 2; ++mt)
#pragma unroll
        for (int nt = 0; nt < 8; ++nt)
#pragma unroll
            for (int r = 0; r < 4; ++r) acc.d[mt][nt][r] = 0.0f;

    for (int kc = 0; kc < C; kc += 16) {
        __syncthreads();
#pragma unroll
        for (int i = 0; i < 2; ++i) {
            int idx = tid + i * 256;
            int row = idx >> 2, k4 = idx & 3;
            size_t ai = (size_t)(m0 + row) * C + kc + k4 * 4;
            float4 ov = *(const float4*)&g_o[ai];
            float4 gp = *(const float4*)&g_proj[3][ai];
            float4 bgv = *(const float4*)&bg[kc + k4 * 4];
            float4 av;
            av.x = ov.x / (1.0f + __expf(-(gp.x + bgv.x)));
            av.y = ov.y / (1.0f + __expf(-(gp.y + bgv.y)));
            av.z = ov.z / (1.0f + __expf(-(gp.z + bgv.z)));
            av.w = ov.w / (1.0f + __expf(-(gp.w + bgv.w)));
            *(float4*)&As[row][k4 * 4] = av;
            float4 b = *(const float4*)&wo[(size_t)row * C + kc + k4 * 4];
            *(float4*)&Bs[row][k4 * 4] = b;
        }
        __syncthreads();
        mma_chunk(As, Bs, wm, wn, g, tq, acc);
    }

#pragma unroll
    for (int mt = 0; mt < 2; ++mt) {
        int r0 = m0 + wm * 32 + mt * 16 + g;
#pragma unroll
        for (int nt = 0; nt < 8; ++nt) {
            int cb = wn * 64 + nt * 8 + 2 * tq;
            float2 bov = *(const float2*)&bo[cb];
            *(float2*)&out[(size_t)r0 * C + cb] =
                make_float2(acc.d[mt][nt][0] + bov.x, acc.d[mt][nt][1] + bov.y);
            *(float2*)&out[(size_t)(r0 + 8) * C + cb] =
                make_float2(acc.d[mt][nt][2] + bov.x, acc.d[mt][nt][3] + bov.y);
        }
    }
}

// ---------------------------------------------------------------------------
extern "C" void kernel_launch(void* const* d_in, const int* in_sizes, int n_in,
                              void* d_out, int out_size) {
    const float* x     = (const float*)d_in[0];
    const float* mask  = (const float*)d_in[1];
    const float* ln_w  = (const float*)d_in[2];
    const float* ln_b  = (const float*)d_in[3];
    const float* w_tri = (const float*)d_in[4];
    const float* wq    = (const float*)d_in[5];
    const float* wk    = (const float*)d_in[6];
    const float* wv    = (const float*)d_in[7];
    const float* wg    = (const float*)d_in[8];
    const float* bg    = (const float*)d_in[9];
    const float* wo    = (const float*)d_in[10];
    const float* bo    = (const float*)d_in[11];
    float* out = (float*)d_out;

    (void)in_sizes; (void)n_in; (void)out_size;

    k_ln_tri<<<NP / 8, 256>>>(x, ln_w, ln_b, w_tri);
    k_proj<<<dim3(NP / 128, 4), 256>>>(wq, wk, wv, wg);
    k_attn<<<dim3(N, H), 256>>>(mask);
    k_out<<<NP / 128, 256>>>(wo, bg, bo, out);
}

// round 6
// speedup vs baseline: 2.2432x; 1.4673x over previous
#include <cuda_runtime.h>
#include <math.h>
#include <stdint.h>

#define N 256
#define C 128
#define H 4
#define D 32
#define NP (N*N)            // 65536 positions
#define EPSV 1e-5f
#define INFV 1000000000.0f
#define KP 20               // smem row pitch for GEMM 16-wide k-chunk
#define QT 64               // attention query tile

// Scratch (static device arrays; no allocation in kernel_launch)
__device__ float g_xn[NP*C];        // layernormed x           32 MB
__device__ float g_tri[H*N*N];      // tri bias [h][q][k]       1 MB
__device__ float g_proj[4][NP*C];   // q, k, v, gate-logits   134 MB
__device__ float g_o[NP*C];         // attention output        32 MB

// round fp32 -> tf32 bit pattern (rna), returned as float bits
__device__ __forceinline__ float tf32r(float x) {
    uint32_t u;
    asm("cvt.rna.tf32.f32 %0, %1;" : "=r"(u) : "f"(x));
    return __uint_as_float(u);
}

__device__ __forceinline__ void mma_tf32(float& d0, float& d1, float& d2, float& d3,
                                         uint32_t a0, uint32_t a1, uint32_t a2, uint32_t a3,
                                         uint32_t b0, uint32_t b1) {
    asm volatile(
        "mma.sync.aligned.m16n8k8.row.col.f32.tf32.tf32.f32 "
        "{%0,%1,%2,%3}, {%4,%5,%6,%7}, {%8,%9}, {%0,%1,%2,%3};\n"
        : "+f"(d0), "+f"(d1), "+f"(d2), "+f"(d3)
        : "r"(a0), "r"(a1), "r"(a2), "r"(a3), "r"(b0), "r"(b1));
}

// ---------------------------------------------------------------------------
// Kernel 1: LayerNorm over C + triangle-bias projection ([h][q][k] layout)
// ---------------------------------------------------------------------------
__global__ void k_ln_tri(const float* __restrict__ x,
                         const float* __restrict__ ln_w,
                         const float* __restrict__ ln_b,
                         const float* __restrict__ w_tri) {
    __shared__ float swt[H*C];
    int tid = threadIdx.x;
    swt[tid]       = w_tri[tid];
    swt[tid + 256] = w_tri[tid + 256];
    __syncthreads();

    int warp = tid >> 5, lane = tid & 31;
    int pos = (blockIdx.x << 3) + warp;

    const float4 a = ((const float4*)(x + (size_t)pos * C))[lane];
    float s  = a.x + a.y + a.z + a.w;
    float s2 = a.x*a.x + a.y*a.y + a.z*a.z + a.w*a.w;
#pragma unroll
    for (int o = 16; o > 0; o >>= 1) {
        s  += __shfl_xor_sync(0xffffffffu, s,  o);
        s2 += __shfl_xor_sync(0xffffffffu, s2, o);
    }
    float mu   = s * (1.0f / C);
    float var  = s2 * (1.0f / C) - mu * mu;
    float rstd = rsqrtf(var + EPSV);

    float4 w = ((const float4*)ln_w)[lane];
    float4 b = ((const float4*)ln_b)[lane];
    float4 xn;
    xn.x = (a.x - mu) * rstd * w.x + b.x;
    xn.y = (a.y - mu) * rstd * w.y + b.y;
    xn.z = (a.z - mu) * rstd * w.z + b.z;
    xn.w = (a.w - mu) * rstd * w.w + b.w;
    ((float4*)(g_xn + (size_t)pos * C))[lane] = xn;

    float t[H];
#pragma unroll
    for (int h = 0; h < H; ++h) {
        const float4 wt = ((const float4*)(swt + h * C))[lane];
        t[h] = xn.x*wt.x + xn.y*wt.y + xn.z*wt.z + xn.w*wt.w;
    }
#pragma unroll
    for (int h = 0; h < H; ++h)
#pragma unroll
        for (int o = 16; o > 0; o >>= 1)
            t[h] += __shfl_xor_sync(0xffffffffu, t[h], o);

    if (lane == 0) {
        int q = pos >> 8, k = pos & 255;
#pragma unroll
        for (int h = 0; h < H; ++h)
            g_tri[(h * N + q) * N + k] = t[h];   // [h][q][k]
    }
}

// ---------------------------------------------------------------------------
// tf32 MMA GEMM core (smem holds pre-rounded tf32 values; frags = raw bits)
// ---------------------------------------------------------------------------
struct MmaAcc { float d[2][8][4]; };   // [mt][nt][reg]

__device__ __forceinline__ void mma_chunk(const float (*As)[KP], const float (*Bs)[KP],
                                          int wm, int wn, int g, int tq, MmaAcc& A) {
#pragma unroll
    for (int ks = 0; ks < 16; ks += 8) {
        uint32_t af[2][4];
#pragma unroll
        for (int mt = 0; mt < 2; ++mt) {
            int r = wm * 32 + mt * 16;
            af[mt][0] = __float_as_uint(As[r + g][ks + tq]);
            af[mt][1] = __float_as_uint(As[r + g + 8][ks + tq]);
            af[mt][2] = __float_as_uint(As[r + g][ks + tq + 4]);
            af[mt][3] = __float_as_uint(As[r + g + 8][ks + tq + 4]);
        }
        uint32_t bf[8][2];
#pragma unroll
        for (int nt = 0; nt < 8; ++nt) {
            int cb = wn * 64 + nt * 8;
            bf[nt][0] = __float_as_uint(Bs[cb + g][ks + tq]);
            bf[nt][1] = __float_as_uint(Bs[cb + g][ks + tq + 4]);
        }
#pragma unroll
        for (int mt = 0; mt < 2; ++mt)
#pragma unroll
            for (int nt = 0; nt < 8; ++nt)
                mma_tf32(A.d[mt][nt][0], A.d[mt][nt][1], A.d[mt][nt][2], A.d[mt][nt][3],
                         af[mt][0], af[mt][1], af[mt][2], af[mt][3],
                         bf[nt][0], bf[nt][1]);
    }
}

// ---------------------------------------------------------------------------
// Kernel 2: QKV + gate projections via tf32 mma. grid=(NP/128, 4).
// ---------------------------------------------------------------------------
__global__ void __launch_bounds__(256)
k_proj(const float* __restrict__ wq, const float* __restrict__ wk,
       const float* __restrict__ wv, const float* __restrict__ wg) {
    __shared__ float As[128][KP];
    __shared__ float Bs[128][KP];
    int tid = threadIdx.x;
    int wsel = blockIdx.y;
    const float* W = (wsel == 0) ? wq : (wsel == 1) ? wk : (wsel == 2) ? wv : wg;
    float* Out = g_proj[wsel];
    int m0 = blockIdx.x * 128;
    int w = tid >> 5, lane = tid & 31;
    int wm = w >> 1, wn = w & 1;
    int g = lane >> 2, tq = lane & 3;

    MmaAcc acc;
#pragma unroll
    for (int mt = 0; mt < 2; ++mt)
#pragma unroll
        for (int nt = 0; nt < 8; ++nt)
#pragma unroll
            for (int r = 0; r < 4; ++r) acc.d[mt][nt][r] = 0.0f;

    for (int kc = 0; kc < C; kc += 16) {
        __syncthreads();
#pragma unroll
        for (int i = 0; i < 2; ++i) {
            int idx = tid + i * 256;            // 0..511
            int row = idx >> 2, k4 = idx & 3;
            float4 a = *(const float4*)&g_xn[(size_t)(m0 + row) * C + kc + k4 * 4];
            As[row][k4*4+0] = tf32r(a.x); As[row][k4*4+1] = tf32r(a.y);
            As[row][k4*4+2] = tf32r(a.z); As[row][k4*4+3] = tf32r(a.w);
            float4 b = *(const float4*)&W[(size_t)row * C + kc + k4 * 4];
            Bs[row][k4*4+0] = tf32r(b.x); Bs[row][k4*4+1] = tf32r(b.y);
            Bs[row][k4*4+2] = tf32r(b.z); Bs[row][k4*4+3] = tf32r(b.w);
        }
        __syncthreads();
        mma_chunk(As, Bs, wm, wn, g, tq, acc);
    }

#pragma unroll
    for (int mt = 0; mt < 2; ++mt) {
        int r0 = m0 + wm * 32 + mt * 16 + g;
#pragma unroll
        for (int nt = 0; nt < 8; ++nt) {
            int cb = wn * 64 + nt * 8 + 2 * tq;
            *(float2*)&Out[(size_t)r0 * C + cb]       = make_float2(acc.d[mt][nt][0], acc.d[mt][nt][1]);
            *(float2*)&Out[(size_t)(r0 + 8) * C + cb] = make_float2(acc.d[mt][nt][2], acc.d[mt][nt][3]);
        }
    }
}

// ---------------------------------------------------------------------------
// Kernel 3: MMA attention. Block = (i, h, 64-query tile). 8 warps.
// S = Q K^T (tf32 mma) + tri + mask bias; full-row softmax; O = P V (tf32 mma).
// ---------------------------------------------------------------------------
struct AttnSmem {
    float Ks[256][36];   // K tile, tf32-rounded          36864 B
    float Vs[256][36];   // V tile, tf32-rounded          36864 B
    float Qs[QT][36];    // Q tile, scaled + rounded       9216 B
    float T[QT][260];    // tri bias -> then P (rounded)  66560 B
    float mb[256];       // mask bias                      1024 B
    float rmax[QT][4];   // per-row partial max (by wn)    1024 B
    float rsum[QT][4];   // per-row partial sum (by wn)    1024 B
};                       // total 152576 B

__global__ void __launch_bounds__(256)
k_attn(const float* __restrict__ mask) {
    extern __shared__ char smraw[];
    AttnSmem* sm = (AttnSmem*)smraw;

    int bx = blockIdx.x;
    int i = bx >> 2, qt = bx & 3;
    int h = blockIdx.y;
    int q0 = qt * QT;
    int tid = threadIdx.x, w = tid >> 5, lane = tid & 31;
    int g = lane >> 2, tq = lane & 3;
    int wm = w >> 2, wn = w & 3;          // S: 2 warps along M(64), 4 along N(256)

    const float* Qg = g_proj[0] + ((size_t)(i * N + q0)) * C + h * D;
    const float* Kg = g_proj[1] + (size_t)i * N * C + h * D;
    const float* Vg = g_proj[2] + (size_t)i * N * C + h * D;

    // ---- load K, V (row = tid), round to tf32 ----
#pragma unroll
    for (int j = 0; j < 8; ++j) {
        float4 kv = *(const float4*)&Kg[(size_t)tid * C + j * 4];
        sm->Ks[tid][j*4+0] = tf32r(kv.x); sm->Ks[tid][j*4+1] = tf32r(kv.y);
        sm->Ks[tid][j*4+2] = tf32r(kv.z); sm->Ks[tid][j*4+3] = tf32r(kv.w);
        float4 vv = *(const float4*)&Vg[(size_t)tid * C + j * 4];
        sm->Vs[tid][j*4+0] = tf32r(vv.x); sm->Vs[tid][j*4+1] = tf32r(vv.y);
        sm->Vs[tid][j*4+2] = tf32r(vv.z); sm->Vs[tid][j*4+3] = tf32r(vv.w);
    }
    // ---- load Q tile (scaled by 1/sqrt(D)) ----
#pragma unroll
    for (int t = 0; t < 2; ++t) {
        int idx = tid + t * 256;           // 0..511
        int row = idx >> 3, j = idx & 7;
        float4 qv = *(const float4*)&Qg[(size_t)row * C + j * 4];
        const float sc = 0.17677669529663688f;
        sm->Qs[row][j*4+0] = tf32r(qv.x * sc); sm->Qs[row][j*4+1] = tf32r(qv.y * sc);
        sm->Qs[row][j*4+2] = tf32r(qv.z * sc); sm->Qs[row][j*4+3] = tf32r(qv.w * sc);
    }
    // ---- load tri tile [q0..q0+63][0..255] into T (fp32) ----
#pragma unroll
    for (int t = 0; t < 16; ++t) {
        int idx = tid + t * 256;           // 0..4095
        int row = idx >> 6, k4 = idx & 63;
        float4 tv = *(const float4*)&g_tri[((size_t)(h * N + q0 + row)) * N + k4 * 4];
        *(float4*)&sm->T[row][k4 * 4] = tv;
    }
    sm->mb[tid] = INFV * (mask[i * N + tid] - 1.0f);
    __syncthreads();

    // ---- S = Q K^T : warp tile 32x64, 2mt x 8nt, k=32 (4 steps) ----
    float sacc[2][8][4];
#pragma unroll
    for (int mt = 0; mt < 2; ++mt)
#pragma unroll
        for (int nt = 0; nt < 8; ++nt)
#pragma unroll
            for (int r = 0; r < 4; ++r) sacc[mt][nt][r] = 0.0f;

#pragma unroll
    for (int ks = 0; ks < 32; ks += 8) {
        uint32_t af[2][4];
#pragma unroll
        for (int mt = 0; mt < 2; ++mt) {
            int r = wm * 32 + mt * 16;
            af[mt][0] = __float_as_uint(sm->Qs[r + g][ks + tq]);
            af[mt][1] = __float_as_uint(sm->Qs[r + g + 8][ks + tq]);
            af[mt][2] = __float_as_uint(sm->Qs[r + g][ks + tq + 4]);
            af[mt][3] = __float_as_uint(sm->Qs[r + g + 8][ks + tq + 4]);
        }
#pragma unroll
        for (int nt = 0; nt < 8; ++nt) {
            int cb = wn * 64 + nt * 8;
            uint32_t b0 = __float_as_uint(sm->Ks[cb + g][ks + tq]);
            uint32_t b1 = __float_as_uint(sm->Ks[cb + g][ks + tq + 4]);
#pragma unroll
            for (int mt = 0; mt < 2; ++mt)
                mma_tf32(sacc[mt][nt][0], sacc[mt][nt][1], sacc[mt][nt][2], sacc[mt][nt][3],
                         af[mt][0], af[mt][1], af[mt][2], af[mt][3], b0, b1);
        }
    }

    // ---- add tri + mask bias; partial row max ----
    float pmax[2][2];
    pmax[0][0] = pmax[0][1] = pmax[1][0] = pmax[1][1] = -3.4e38f;
#pragma unroll
    for (int mt = 0; mt < 2; ++mt) {
        int r0 = wm * 32 + mt * 16 + g;
#pragma unroll
        for (int nt = 0; nt < 8; ++nt) {
            int c0 = wn * 64 + nt * 8 + 2 * tq;
            float m0v = sm->mb[c0], m1v = sm->mb[c0 + 1];
            sacc[mt][nt][0] += sm->T[r0][c0]     + m0v;
            sacc[mt][nt][1] += sm->T[r0][c0 + 1] + m1v;
            sacc[mt][nt][2] += sm->T[r0 + 8][c0]     + m0v;
            sacc[mt][nt][3] += sm->T[r0 + 8][c0 + 1] + m1v;
            pmax[mt][0] = fmaxf(pmax[mt][0], fmaxf(sacc[mt][nt][0], sacc[mt][nt][1]));
            pmax[mt][1] = fmaxf(pmax[mt][1], fmaxf(sacc[mt][nt][2], sacc[mt][nt][3]));
        }
    }
#pragma unroll
    for (int mt = 0; mt < 2; ++mt)
#pragma unroll
        for (int rh = 0; rh < 2; ++rh) {
            float v = pmax[mt][rh];
            v = fmaxf(v, __shfl_xor_sync(0xffffffffu, v, 1));
            v = fmaxf(v, __shfl_xor_sync(0xffffffffu, v, 2));
            pmax[mt][rh] = v;
        }
    if (tq == 0) {
#pragma unroll
        for (int mt = 0; mt < 2; ++mt) {
            int r0 = wm * 32 + mt * 16 + g;
            sm->rmax[r0][wn]     = pmax[mt][0];
            sm->rmax[r0 + 8][wn] = pmax[mt][1];
        }
    }
    __syncthreads();

    // ---- exp + write P (tf32-rounded) + partial row sums ----
    float psum[2][2] = {{0.0f, 0.0f}, {0.0f, 0.0f}};
#pragma unroll
    for (int mt = 0; mt < 2; ++mt) {
        int r0 = wm * 32 + mt * 16 + g;
        float4 m4a = *(float4*)sm->rmax[r0];
        float rm0 = fmaxf(fmaxf(m4a.x, m4a.y), fmaxf(m4a.z, m4a.w));
        float4 m4b = *(float4*)sm->rmax[r0 + 8];
        float rm1 = fmaxf(fmaxf(m4b.x, m4b.y), fmaxf(m4b.z, m4b.w));
#pragma unroll
        for (int nt = 0; nt < 8; ++nt) {
            int c0 = wn * 64 + nt * 8 + 2 * tq;
            float p0 = tf32r(__expf(sacc[mt][nt][0] - rm0));
            float p1 = tf32r(__expf(sacc[mt][nt][1] - rm0));
            float p2 = tf32r(__expf(sacc[mt][nt][2] - rm1));
            float p3 = tf32r(__expf(sacc[mt][nt][3] - rm1));
            psum[mt][0] += p0 + p1;
            psum[mt][1] += p2 + p3;
            sm->T[r0][c0] = p0;     sm->T[r0][c0 + 1] = p1;
            sm->T[r0 + 8][c0] = p2; sm->T[r0 + 8][c0 + 1] = p3;
        }
    }
#pragma unroll
    for (int mt = 0; mt < 2; ++mt)
#pragma unroll
        for (int rh = 0; rh < 2; ++rh) {
            float v = psum[mt][rh];
            v += __shfl_xor_sync(0xffffffffu, v, 1);
            v += __shfl_xor_sync(0xffffffffu, v, 2);
            psum[mt][rh] = v;
        }
    if (tq == 0) {
#pragma unroll
        for (int mt = 0; mt < 2; ++mt) {
            int r0 = wm * 32 + mt * 16 + g;
            sm->rsum[r0][wn]     = psum[mt][0];
            sm->rsum[r0 + 8][wn] = psum[mt][1];
        }
    }
    __syncthreads();

    // ---- O = P V : warp tile 32x8 (same rows as S phase), k=256 (32 steps) ----
    int nb = wn * 8;
    float oacc[2][4] = {{0,0,0,0},{0,0,0,0}};
#pragma unroll
    for (int ks8 = 0; ks8 < 32; ++ks8) {
        int kk = ks8 * 8;
        uint32_t b0 = __float_as_uint(sm->Vs[kk + tq][nb + g]);
        uint32_t b1 = __float_as_uint(sm->Vs[kk + tq + 4][nb + g]);
#pragma unroll
        for (int mt = 0; mt < 2; ++mt) {
            int r0 = wm * 32 + mt * 16 + g;
            uint32_t a0 = __float_as_uint(sm->T[r0][kk + tq]);
            uint32_t a1 = __float_as_uint(sm->T[r0 + 8][kk + tq]);
            uint32_t a2 = __float_as_uint(sm->T[r0][kk + tq + 4]);
            uint32_t a3 = __float_as_uint(sm->T[r0 + 8][kk + tq + 4]);
            mma_tf32(oacc[mt][0], oacc[mt][1], oacc[mt][2], oacc[mt][3],
                     a0, a1, a2, a3, b0, b1);
        }
    }

    // ---- epilogue: normalize by row sums, store ----
#pragma unroll
    for (int mt = 0; mt < 2; ++mt) {
        int r0 = wm * 32 + mt * 16 + g;
        float4 s0 = *(float4*)sm->rsum[r0];
        float inv0 = 1.0f / (s0.x + s0.y + s0.z + s0.w);
        float4 s1 = *(float4*)sm->rsum[r0 + 8];
        float inv1 = 1.0f / (s1.x + s1.y + s1.z + s1.w);
        int col = nb + 2 * tq;
        size_t b0a = ((size_t)(i * N + q0 + r0)) * C + h * D + col;
        *(float2*)&g_o[b0a] = make_float2(oacc[mt][0] * inv0, oacc[mt][1] * inv0);
        size_t b1a = ((size_t)(i * N + q0 + r0 + 8)) * C + h * D + col;
        *(float2*)&g_o[b1a] = make_float2(oacc[mt][2] * inv1, oacc[mt][3] * inv1);
    }
}

// ---------------------------------------------------------------------------
// Kernel 4: gated output projection via tf32 mma. grid=(NP/128).
// ---------------------------------------------------------------------------
__global__ void __launch_bounds__(256)
k_out(const float* __restrict__ wo, const float* __restrict__ bg,
      const float* __restrict__ bo, float* __restrict__ out) {
    __shared__ float As[128][KP];
    __shared__ float Bs[128][KP];
    int tid = threadIdx.x;
    int m0 = blockIdx.x * 128;
    int w = tid >> 5, lane = tid & 31;
    int wm = w >> 1, wn = w & 1;
    int g = lane >> 2, tq = lane & 3;

    MmaAcc acc;
#pragma unroll
    for (int mt = 0; mt < 2; ++mt)
#pragma unroll
        for (int nt = 0; nt < 8; ++nt)
#pragma unroll
            for (int r = 0; r < 4; ++r) acc.d[mt][nt][r] = 0.0f;

    for (int kc = 0; kc < C; kc += 16) {
        __syncthreads();
#pragma unroll
        for (int i = 0; i < 2; ++i) {
            int idx = tid + i * 256;
            int row = idx >> 2, k4 = idx & 3;
            size_t ai = (size_t)(m0 + row) * C + kc + k4 * 4;
            float4 ov = *(const float4*)&g_o[ai];
            float4 gp = *(const float4*)&g_proj[3][ai];
            float4 bgv = *(const float4*)&bg[kc + k4 * 4];
            As[row][k4*4+0] = tf32r(ov.x / (1.0f + __expf(-(gp.x + bgv.x))));
            As[row][k4*4+1] = tf32r(ov.y / (1.0f + __expf(-(gp.y + bgv.y))));
            As[row][k4*4+2] = tf32r(ov.z / (1.0f + __expf(-(gp.z + bgv.z))));
            As[row][k4*4+3] = tf32r(ov.w / (1.0f + __expf(-(gp.w + bgv.w))));
            float4 b = *(const float4*)&wo[(size_t)row * C + kc + k4 * 4];
            Bs[row][k4*4+0] = tf32r(b.x); Bs[row][k4*4+1] = tf32r(b.y);
            Bs[row][k4*4+2] = tf32r(b.z); Bs[row][k4*4+3] = tf32r(b.w);
        }
        __syncthreads();
        mma_chunk(As, Bs, wm, wn, g, tq, acc);
    }

#pragma unroll
    for (int mt = 0; mt < 2; ++mt) {
        int r0 = m0 + wm * 32 + mt * 16 + g;
#pragma unroll
        for (int nt = 0; nt < 8; ++nt) {
            int cb = wn * 64 + nt * 8 + 2 * tq;
            float2 bov = *(const float2*)&bo[cb];
            *(float2*)&out[(size_t)r0 * C + cb] =
                make_float2(acc.d[mt][nt][0] + bov.x, acc.d[mt][nt][1] + bov.y);
            *(float2*)&out[(size_t)(r0 + 8) * C + cb] =
                make_float2(acc.d[mt][nt][2] + bov.x, acc.d[mt][nt][3] + bov.y);
        }
    }
}

// ---------------------------------------------------------------------------
extern "C" void kernel_launch(void* const* d_in, const int* in_sizes, int n_in,
                              void* d_out, int out_size) {
    const float* x     = (const float*)d_in[0];
    const float* mask  = (const float*)d_in[1];
    const float* ln_w  = (const float*)d_in[2];
    const float* ln_b  = (const float*)d_in[3];
    const float* w_tri = (const float*)d_in[4];
    const float* wq    = (const float*)d_in[5];
    const float* wk    = (const float*)d_in[6];
    const float* wv    = (const float*)d_in[7];
    const float* wg    = (const float*)d_in[8];
    const float* bg    = (const float*)d_in[9];
    const float* wo    = (const float*)d_in[10];
    const float* bo    = (const float*)d_in[11];
    float* out = (float*)d_out;

    (void)in_sizes; (void)n_in; (void)out_size;

    cudaFuncSetAttribute(k_attn, cudaFuncAttributeMaxDynamicSharedMemorySize,
                         (int)sizeof(AttnSmem));

    k_ln_tri<<<NP / 8, 256>>>(x, ln_w, ln_b, w_tri);
    k_proj<<<dim3(NP / 128, 4), 256>>>(wq, wk, wv, wg);
    k_attn<<<dim3((N / QT) * N, H), 256, sizeof(AttnSmem)>>>(mask);
    k_out<<<NP / 128, 256>>>(wo, bg, bo, out);
}

// round 7
// speedup vs baseline: 2.5729x; 1.1470x over previous
#include <cuda_runtime.h>
#include <math.h>
#include <stdint.h>

#define N 256
#define C 128
#define H 4
#define D 32
#define NP (N*N)            // 65536 positions
#define EPSV 1e-5f
#define INFV 1000000000.0f
#define QT 64               // attention query tile

// Scratch (static device arrays; no allocation in kernel_launch)
__device__ float g_xn[NP*C];        // layernormed x           32 MB
__device__ float g_tri[H*N*N];      // tri bias [h][q][k]       1 MB
__device__ float g_proj[4][NP*C];   // q, k, v, gate-logits   134 MB
__device__ float g_o[NP*C];         // attention output        32 MB

// round fp32 -> tf32 bit pattern (rna), returned as float bits
__device__ __forceinline__ float tf32r(float x) {
    uint32_t u;
    asm("cvt.rna.tf32.f32 %0, %1;" : "=r"(u) : "f"(x));
    return __uint_as_float(u);
}

__device__ __forceinline__ void mma_tf32(float& d0, float& d1, float& d2, float& d3,
                                         uint32_t a0, uint32_t a1, uint32_t a2, uint32_t a3,
                                         uint32_t b0, uint32_t b1) {
    asm volatile(
        "mma.sync.aligned.m16n8k8.row.col.f32.tf32.tf32.f32 "
        "{%0,%1,%2,%3}, {%4,%5,%6,%7}, {%8,%9}, {%0,%1,%2,%3};\n"
        : "+f"(d0), "+f"(d1), "+f"(d2), "+f"(d3)
        : "r"(a0), "r"(a1), "r"(a2), "r"(a3), "r"(b0), "r"(b1));
}

// ---------------------------------------------------------------------------
// Kernel 1: LayerNorm over C + triangle-bias projection ([h][q][k] layout)
// ---------------------------------------------------------------------------
__global__ void k_ln_tri(const float* __restrict__ x,
                         const float* __restrict__ ln_w,
                         const float* __restrict__ ln_b,
                         const float* __restrict__ w_tri) {
    __shared__ float swt[H*C];
    int tid = threadIdx.x;
    swt[tid]       = w_tri[tid];
    swt[tid + 256] = w_tri[tid + 256];
    __syncthreads();

    int warp = tid >> 5, lane = tid & 31;
    int pos = (blockIdx.x << 3) + warp;

    const float4 a = ((const float4*)(x + (size_t)pos * C))[lane];
    float s  = a.x + a.y + a.z + a.w;
    float s2 = a.x*a.x + a.y*a.y + a.z*a.z + a.w*a.w;
#pragma unroll
    for (int o = 16; o > 0; o >>= 1) {
        s  += __shfl_xor_sync(0xffffffffu, s,  o);
        s2 += __shfl_xor_sync(0xffffffffu, s2, o);
    }
    float mu   = s * (1.0f / C);
    float var  = s2 * (1.0f / C) - mu * mu;
    float rstd = rsqrtf(var + EPSV);

    float4 w = ((const float4*)ln_w)[lane];
    float4 b = ((const float4*)ln_b)[lane];
    float4 xn;
    xn.x = (a.x - mu) * rstd * w.x + b.x;
    xn.y = (a.y - mu) * rstd * w.y + b.y;
    xn.z = (a.z - mu) * rstd * w.z + b.z;
    xn.w = (a.w - mu) * rstd * w.w + b.w;
    ((float4*)(g_xn + (size_t)pos * C))[lane] = xn;

    float t[H];
#pragma unroll
    for (int h = 0; h < H; ++h) {
        const float4 wt = ((const float4*)(swt + h * C))[lane];
        t[h] = xn.x*wt.x + xn.y*wt.y + xn.z*wt.z + xn.w*wt.w;
    }
#pragma unroll
    for (int h = 0; h < H; ++h)
#pragma unroll
        for (int o = 16; o > 0; o >>= 1)
            t[h] += __shfl_xor_sync(0xffffffffu, t[h], o);

    if (lane == 0) {
        int q = pos >> 8, k = pos & 255;
#pragma unroll
        for (int h = 0; h < H; ++h)
            g_tri[(h * N + q) * N + k] = t[h];   // [h][q][k]
    }
}

// ---------------------------------------------------------------------------
// GEMM smem: B fully resident (pitch 132), A double-buffered 32-wide chunks
// ---------------------------------------------------------------------------
struct GemmSmem {
    float Bs[128][132];     // 67584 B
    float As[2][128][36];   // 36864 B
};                          // 104448 B

struct MmaAcc { float d[2][8][4]; };   // [mt][nt][reg]

__device__ __forceinline__ void mma_chunk32(const float (*As)[36], const float (*Bs)[132],
                                            int cbase, int wm, int wn, int g, int tq,
                                            MmaAcc& A) {
#pragma unroll
    for (int ks = 0; ks < 32; ks += 8) {
        uint32_t af[2][4];
#pragma unroll
        for (int mt = 0; mt < 2; ++mt) {
            int r = wm * 32 + mt * 16;
            af[mt][0] = __float_as_uint(As[r + g][ks + tq]);
            af[mt][1] = __float_as_uint(As[r + g + 8][ks + tq]);
            af[mt][2] = __float_as_uint(As[r + g][ks + tq + 4]);
            af[mt][3] = __float_as_uint(As[r + g + 8][ks + tq + 4]);
        }
#pragma unroll
        for (int nt = 0; nt < 8; ++nt) {
            int cb = wn * 64 + nt * 8;
            uint32_t b0 = __float_as_uint(Bs[cb + g][cbase + ks + tq]);
            uint32_t b1 = __float_as_uint(Bs[cb + g][cbase + ks + tq + 4]);
#pragma unroll
            for (int mt = 0; mt < 2; ++mt)
                mma_tf32(A.d[mt][nt][0], A.d[mt][nt][1], A.d[mt][nt][2], A.d[mt][nt][3],
                         af[mt][0], af[mt][1], af[mt][2], af[mt][3], b0, b1);
        }
    }
}

// ---------------------------------------------------------------------------
// Kernel 2: QKV + gate projections. grid=(NP/128, 4). B resident, A pipelined.
// ---------------------------------------------------------------------------
__global__ void __launch_bounds__(256)
k_proj(const float* __restrict__ wq, const float* __restrict__ wk,
       const float* __restrict__ wv, const float* __restrict__ wg) {
    extern __shared__ char smraw[];
    GemmSmem* sm = (GemmSmem*)smraw;
    int tid = threadIdx.x;
    int wsel = blockIdx.y;
    const float* W = (wsel == 0) ? wq : (wsel == 1) ? wk : (wsel == 2) ? wv : wg;
    float* Out = g_proj[wsel];
    int m0 = blockIdx.x * 128;
    int w = tid >> 5, lane = tid & 31;
    int wm = w >> 1, wn = w & 1;
    int g = lane >> 2, tq = lane & 3;

    // stage full B (tf32-rounded)
#pragma unroll
    for (int t = 0; t < 16; ++t) {
        int idx = tid + t * 256;          // 0..4095
        int row = idx >> 5, j4 = idx & 31;
        float4 b = *(const float4*)&W[(size_t)row * C + j4 * 4];
        float4 r = {tf32r(b.x), tf32r(b.y), tf32r(b.z), tf32r(b.w)};
        *(float4*)&sm->Bs[row][j4 * 4] = r;
    }
    // stage A chunk 0
#pragma unroll
    for (int t = 0; t < 4; ++t) {
        int idx = tid + t * 256;          // 0..1023
        int row = idx >> 3, j = idx & 7;
        float4 a = *(const float4*)&g_xn[(size_t)(m0 + row) * C + j * 4];
        float4 r = {tf32r(a.x), tf32r(a.y), tf32r(a.z), tf32r(a.w)};
        *(float4*)&sm->As[0][row][j * 4] = r;
    }
    __syncthreads();

    MmaAcc acc;
#pragma unroll
    for (int mt = 0; mt < 2; ++mt)
#pragma unroll
        for (int nt = 0; nt < 8; ++nt)
#pragma unroll
            for (int r = 0; r < 4; ++r) acc.d[mt][nt][r] = 0.0f;

#pragma unroll
    for (int kc = 0; kc < 4; ++kc) {
        float4 pre[4];
        if (kc < 3) {
#pragma unroll
            for (int t = 0; t < 4; ++t) {
                int idx = tid + t * 256;
                int row = idx >> 3, j = idx & 7;
                pre[t] = *(const float4*)&g_xn[(size_t)(m0 + row) * C + (kc + 1) * 32 + j * 4];
            }
        }
        mma_chunk32(sm->As[kc & 1], sm->Bs, kc * 32, wm, wn, g, tq, acc);
        if (kc < 3) {
#pragma unroll
            for (int t = 0; t < 4; ++t) {
                int idx = tid + t * 256;
                int row = idx >> 3, j = idx & 7;
                float4 r = {tf32r(pre[t].x), tf32r(pre[t].y), tf32r(pre[t].z), tf32r(pre[t].w)};
                *(float4*)&sm->As[(kc + 1) & 1][row][j * 4] = r;
            }
            __syncthreads();
        }
    }

#pragma unroll
    for (int mt = 0; mt < 2; ++mt) {
        int r0 = m0 + wm * 32 + mt * 16 + g;
#pragma unroll
        for (int nt = 0; nt < 8; ++nt) {
            int cb = wn * 64 + nt * 8 + 2 * tq;
            *(float2*)&Out[(size_t)r0 * C + cb]       = make_float2(acc.d[mt][nt][0], acc.d[mt][nt][1]);
            *(float2*)&Out[(size_t)(r0 + 8) * C + cb] = make_float2(acc.d[mt][nt][2], acc.d[mt][nt][3]);
        }
    }
}

// ---------------------------------------------------------------------------
// Kernel 3: MMA attention. Block = (i, h); loops 4 query tiles, K/V loaded once.
// ---------------------------------------------------------------------------
struct AttnSmem {
    float Ks[256][36];   // K tile, tf32-rounded          36864 B
    float Vs[256][36];   // V tile, tf32-rounded          36864 B
    float Qs[QT][36];    // Q tile, scaled + rounded       9216 B
    float T[QT][260];    // tri bias -> then P (rounded)  66560 B
    float mb[256];       // mask bias                      1024 B
    float rmax[QT][4];   // per-row partial max (by wn)    1024 B
    float rsum[QT][4];   // per-row partial sum (by wn)    1024 B
};                       // total 152576 B

__global__ void __launch_bounds__(256)
k_attn(const float* __restrict__ mask) {
    extern __shared__ char smraw[];
    AttnSmem* sm = (AttnSmem*)smraw;

    int i = blockIdx.x, h = blockIdx.y;
    int tid = threadIdx.x, w = tid >> 5, lane = tid & 31;
    int g = lane >> 2, tq = lane & 3;
    int wm = w >> 2, wn = w & 3;          // S: 2 warps along M(64), 4 along N(256)

    const float* Kg = g_proj[1] + (size_t)i * N * C + h * D;
    const float* Vg = g_proj[2] + (size_t)i * N * C + h * D;

    // ---- load K, V (row = tid), round to tf32; mask bias ----
#pragma unroll
    for (int j = 0; j < 8; ++j) {
        float4 kv = *(const float4*)&Kg[(size_t)tid * C + j * 4];
        sm->Ks[tid][j*4+0] = tf32r(kv.x); sm->Ks[tid][j*4+1] = tf32r(kv.y);
        sm->Ks[tid][j*4+2] = tf32r(kv.z); sm->Ks[tid][j*4+3] = tf32r(kv.w);
        float4 vv = *(const float4*)&Vg[(size_t)tid * C + j * 4];
        sm->Vs[tid][j*4+0] = tf32r(vv.x); sm->Vs[tid][j*4+1] = tf32r(vv.y);
        sm->Vs[tid][j*4+2] = tf32r(vv.z); sm->Vs[tid][j*4+3] = tf32r(vv.w);
    }
    sm->mb[tid] = INFV * (mask[i * N + tid] - 1.0f);

    for (int qt = 0; qt < 4; ++qt) {
        int q0 = qt * QT;
        __syncthreads();   // K/V/mb visible (iter 0); T/Qs/rsum free (iters > 0)

        const float* Qg = g_proj[0] + ((size_t)(i * N + q0)) * C + h * D;
        // ---- load Q tile (scaled by 1/sqrt(D)) ----
#pragma unroll
        for (int t = 0; t < 2; ++t) {
            int idx = tid + t * 256;           // 0..511
            int row = idx >> 3, j = idx & 7;
            float4 qv = *(const float4*)&Qg[(size_t)row * C + j * 4];
            const float sc = 0.17677669529663688f;
            sm->Qs[row][j*4+0] = tf32r(qv.x * sc); sm->Qs[row][j*4+1] = tf32r(qv.y * sc);
            sm->Qs[row][j*4+2] = tf32r(qv.z * sc); sm->Qs[row][j*4+3] = tf32r(qv.w * sc);
        }
        // ---- load tri tile [q0..q0+63][0..255] into T (fp32) ----
#pragma unroll
        for (int t = 0; t < 16; ++t) {
            int idx = tid + t * 256;           // 0..4095
            int row = idx >> 6, k4 = idx & 63;
            float4 tv = *(const float4*)&g_tri[((size_t)(h * N + q0 + row)) * N + k4 * 4];
            *(float4*)&sm->T[row][k4 * 4] = tv;
        }
        __syncthreads();

        // ---- S = Q K^T : warp tile 32x64, 2mt x 8nt, k=32 ----
        float sacc[2][8][4];
#pragma unroll
        for (int mt = 0; mt < 2; ++mt)
#pragma unroll
            for (int nt = 0; nt < 8; ++nt)
#pragma unroll
                for (int r = 0; r < 4; ++r) sacc[mt][nt][r] = 0.0f;

#pragma unroll
        for (int ks = 0; ks < 32; ks += 8) {
            uint32_t af[2][4];
#pragma unroll
            for (int mt = 0; mt < 2; ++mt) {
                int r = wm * 32 + mt * 16;
                af[mt][0] = __float_as_uint(sm->Qs[r + g][ks + tq]);
                af[mt][1] = __float_as_uint(sm->Qs[r + g + 8][ks + tq]);
                af[mt][2] = __float_as_uint(sm->Qs[r + g][ks + tq + 4]);
                af[mt][3] = __float_as_uint(sm->Qs[r + g + 8][ks + tq + 4]);
            }
#pragma unroll
            for (int nt = 0; nt < 8; ++nt) {
                int cb = wn * 64 + nt * 8;
                uint32_t b0 = __float_as_uint(sm->Ks[cb + g][ks + tq]);
                uint32_t b1 = __float_as_uint(sm->Ks[cb + g][ks + tq + 4]);
#pragma unroll
                for (int mt = 0; mt < 2; ++mt)
                    mma_tf32(sacc[mt][nt][0], sacc[mt][nt][1], sacc[mt][nt][2], sacc[mt][nt][3],
                             af[mt][0], af[mt][1], af[mt][2], af[mt][3], b0, b1);
            }
        }

        // ---- add tri + mask bias; partial row max ----
        float pmax[2][2];
        pmax[0][0] = pmax[0][1] = pmax[1][0] = pmax[1][1] = -3.4e38f;
#pragma unroll
        for (int mt = 0; mt < 2; ++mt) {
            int r0 = wm * 32 + mt * 16 + g;
#pragma unroll
            for (int nt = 0; nt < 8; ++nt) {
                int c0 = wn * 64 + nt * 8 + 2 * tq;
                float m0v = sm->mb[c0], m1v = sm->mb[c0 + 1];
                sacc[mt][nt][0] += sm->T[r0][c0]     + m0v;
                sacc[mt][nt][1] += sm->T[r0][c0 + 1] + m1v;
                sacc[mt][nt][2] += sm->T[r0 + 8][c0]     + m0v;
                sacc[mt][nt][3] += sm->T[r0 + 8][c0 + 1] + m1v;
                pmax[mt][0] = fmaxf(pmax[mt][0], fmaxf(sacc[mt][nt][0], sacc[mt][nt][1]));
                pmax[mt][1] = fmaxf(pmax[mt][1], fmaxf(sacc[mt][nt][2], sacc[mt][nt][3]));
            }
        }
#pragma unroll
        for (int mt = 0; mt < 2; ++mt)
#pragma unroll
            for (int rh = 0; rh < 2; ++rh) {
                float v = pmax[mt][rh];
                v = fmaxf(v, __shfl_xor_sync(0xffffffffu, v, 1));
                v = fmaxf(v, __shfl_xor_sync(0xffffffffu, v, 2));
                pmax[mt][rh] = v;
            }
        if (tq == 0) {
#pragma unroll
            for (int mt = 0; mt < 2; ++mt) {
                int r0 = wm * 32 + mt * 16 + g;
                sm->rmax[r0][wn]     = pmax[mt][0];
                sm->rmax[r0 + 8][wn] = pmax[mt][1];
            }
        }
        __syncthreads();

        // ---- exp + write P (tf32-rounded) + partial row sums ----
        float psum[2][2] = {{0.0f, 0.0f}, {0.0f, 0.0f}};
#pragma unroll
        for (int mt = 0; mt < 2; ++mt) {
            int r0 = wm * 32 + mt * 16 + g;
            float4 m4a = *(float4*)sm->rmax[r0];
            float rm0 = fmaxf(fmaxf(m4a.x, m4a.y), fmaxf(m4a.z, m4a.w));
            float4 m4b = *(float4*)sm->rmax[r0 + 8];
            float rm1 = fmaxf(fmaxf(m4b.x, m4b.y), fmaxf(m4b.z, m4b.w));
#pragma unroll
            for (int nt = 0; nt < 8; ++nt) {
                int c0 = wn * 64 + nt * 8 + 2 * tq;
                float p0 = tf32r(__expf(sacc[mt][nt][0] - rm0));
                float p1 = tf32r(__expf(sacc[mt][nt][1] - rm0));
                float p2 = tf32r(__expf(sacc[mt][nt][2] - rm1));
                float p3 = tf32r(__expf(sacc[mt][nt][3] - rm1));
                psum[mt][0] += p0 + p1;
                psum[mt][1] += p2 + p3;
                sm->T[r0][c0] = p0;     sm->T[r0][c0 + 1] = p1;
                sm->T[r0 + 8][c0] = p2; sm->T[r0 + 8][c0 + 1] = p3;
            }
        }
#pragma unroll
        for (int mt = 0; mt < 2; ++mt)
#pragma unroll
            for (int rh = 0; rh < 2; ++rh) {
                float v = psum[mt][rh];
                v += __shfl_xor_sync(0xffffffffu, v, 1);
                v += __shfl_xor_sync(0xffffffffu, v, 2);
                psum[mt][rh] = v;
            }
        if (tq == 0) {
#pragma unroll
            for (int mt = 0; mt < 2; ++mt) {
                int r0 = wm * 32 + mt * 16 + g;
                sm->rsum[r0][wn]     = psum[mt][0];
                sm->rsum[r0 + 8][wn] = psum[mt][1];
            }
        }
        __syncthreads();

        // ---- O = P V : warp tile 32x8, k=256 ----
        int nb = wn * 8;
        float oacc[2][4] = {{0,0,0,0},{0,0,0,0}};
#pragma unroll
        for (int ks8 = 0; ks8 < 32; ++ks8) {
            int kk = ks8 * 8;
            uint32_t b0 = __float_as_uint(sm->Vs[kk + tq][nb + g]);
            uint32_t b1 = __float_as_uint(sm->Vs[kk + tq + 4][nb + g]);
#pragma unroll
            for (int mt = 0; mt < 2; ++mt) {
                int r0 = wm * 32 + mt * 16 + g;
                uint32_t a0 = __float_as_uint(sm->T[r0][kk + tq]);
                uint32_t a1 = __float_as_uint(sm->T[r0 + 8][kk + tq]);
                uint32_t a2 = __float_as_uint(sm->T[r0][kk + tq + 4]);
                uint32_t a3 = __float_as_uint(sm->T[r0 + 8][kk + tq + 4]);
                mma_tf32(oacc[mt][0], oacc[mt][1], oacc[mt][2], oacc[mt][3],
                         a0, a1, a2, a3, b0, b1);
            }
        }

        // ---- epilogue: normalize by row sums, store ----
#pragma unroll
        for (int mt = 0; mt < 2; ++mt) {
            int r0 = wm * 32 + mt * 16 + g;
            float4 s0 = *(float4*)sm->rsum[r0];
            float inv0 = 1.0f / (s0.x + s0.y + s0.z + s0.w);
            float4 s1 = *(float4*)sm->rsum[r0 + 8];
            float inv1 = 1.0f / (s1.x + s1.y + s1.z + s1.w);
            int col = nb + 2 * tq;
            size_t b0a = ((size_t)(i * N + q0 + r0)) * C + h * D + col;
            *(float2*)&g_o[b0a] = make_float2(oacc[mt][0] * inv0, oacc[mt][1] * inv0);
            size_t b1a = ((size_t)(i * N + q0 + r0 + 8)) * C + h * D + col;
            *(float2*)&g_o[b1a] = make_float2(oacc[mt][2] * inv1, oacc[mt][3] * inv1);
        }
    }
}

// ---------------------------------------------------------------------------
// Kernel 4: gated output projection. grid=(NP/128). B resident, A staged.
// ---------------------------------------------------------------------------
__global__ void __launch_bounds__(256)
k_out(const float* __restrict__ wo, const float* __restrict__ bg,
      const float* __restrict__ bo, float* __restrict__ out) {
    extern __shared__ char smraw[];
    GemmSmem* sm = (GemmSmem*)smraw;
    int tid = threadIdx.x;
    int m0 = blockIdx.x * 128;
    int w = tid >> 5, lane = tid & 31;
    int wm = w >> 1, wn = w & 1;
    int g = lane >> 2, tq = lane & 3;

    // stage full B (wo, tf32-rounded)
#pragma unroll
    for (int t = 0; t < 16; ++t) {
        int idx = tid + t * 256;
        int row = idx >> 5, j4 = idx & 31;
        float4 b = *(const float4*)&wo[(size_t)row * C + j4 * 4];
        float4 r = {tf32r(b.x), tf32r(b.y), tf32r(b.z), tf32r(b.w)};
        *(float4*)&sm->Bs[row][j4 * 4] = r;
    }
    // stage A chunk 0 (gated)
#pragma unroll
    for (int t = 0; t < 4; ++t) {
        int idx = tid + t * 256;
        int row = idx >> 3, j = idx & 7;
        int col = j * 4;
        size_t ai = (size_t)(m0 + row) * C + col;
        float4 ov = *(const float4*)&g_o[ai];
        float4 gp = *(const float4*)&g_proj[3][ai];
        float4 bgv = *(const float4*)&bg[col];
        float4 r;
        r.x = tf32r(ov.x / (1.0f + __expf(-(gp.x + bgv.x))));
        r.y = tf32r(ov.y / (1.0f + __expf(-(gp.y + bgv.y))));
        r.z = tf32r(ov.z / (1.0f + __expf(-(gp.z + bgv.z))));
        r.w = tf32r(ov.w / (1.0f + __expf(-(gp.w + bgv.w))));
        *(float4*)&sm->As[0][row][j * 4] = r;
    }
    __syncthreads();

    MmaAcc acc;
#pragma unroll
    for (int mt = 0; mt < 2; ++mt)
#pragma unroll
        for (int nt = 0; nt < 8; ++nt)
#pragma unroll
            for (int r = 0; r < 4; ++r) acc.d[mt][nt][r] = 0.0f;

#pragma unroll
    for (int kc = 0; kc < 4; ++kc) {
        mma_chunk32(sm->As[kc & 1], sm->Bs, kc * 32, wm, wn, g, tq, acc);
        if (kc < 3) {
#pragma unroll
            for (int t = 0; t < 4; ++t) {
                int idx = tid + t * 256;
                int row = idx >> 3, j = idx & 7;
                int col = (kc + 1) * 32 + j * 4;
                size_t ai = (size_t)(m0 + row) * C + col;
                float4 ov = *(const float4*)&g_o[ai];
                float4 gp = *(const float4*)&g_proj[3][ai];
                float4 bgv = *(const float4*)&bg[col];
                float4 r;
                r.x = tf32r(ov.x / (1.0f + __expf(-(gp.x + bgv.x))));
                r.y = tf32r(ov.y / (1.0f + __expf(-(gp.y + bgv.y))));
                r.z = tf32r(ov.z / (1.0f + __expf(-(gp.z + bgv.z))));
                r.w = tf32r(ov.w / (1.0f + __expf(-(gp.w + bgv.w))));
                *(float4*)&sm->As[(kc + 1) & 1][row][j * 4] = r;
            }
            __syncthreads();
        }
    }

#pragma unroll
    for (int mt = 0; mt < 2; ++mt) {
        int r0 = m0 + wm * 32 + mt * 16 + g;
#pragma unroll
        for (int nt = 0; nt < 8; ++nt) {
            int cb = wn * 64 + nt * 8 + 2 * tq;
            float2 bov = *(const float2*)&bo[cb];
            *(float2*)&out[(size_t)r0 * C + cb] =
                make_float2(acc.d[mt][nt][0] + bov.x, acc.d[mt][nt][1] + bov.y);
            *(float2*)&out[(size_t)(r0 + 8) * C + cb] =
                make_float2(acc.d[mt][nt][2] + bov.x, acc.d[mt][nt][3] + bov.y);
        }
    }
}

// ---------------------------------------------------------------------------
extern "C" void kernel_launch(void* const* d_in, const int* in_sizes, int n_in,
                              void* d_out, int out_size) {
    const float* x     = (const float*)d_in[0];
    const float* mask  = (const float*)d_in[1];
    const float* ln_w  = (const float*)d_in[2];
    const float* ln_b  = (const float*)d_in[3];
    const float* w_tri = (const float*)d_in[4];
    const float* wq    = (const float*)d_in[5];
    const float* wk    = (const float*)d_in[6];
    const float* wv    = (const float*)d_in[7];
    const float* wg    = (const float*)d_in[8];
    const float* bg    = (const float*)d_in[9];
    const float* wo    = (const float*)d_in[10];
    const float* bo    = (const float*)d_in[11];
    float* out = (float*)d_out;

    (void)in_sizes; (void)n_in; (void)out_size;

    cudaFuncSetAttribute(k_proj, cudaFuncAttributeMaxDynamicSharedMemorySize,
                         (int)sizeof(GemmSmem));
    cudaFuncSetAttribute(k_out, cudaFuncAttributeMaxDynamicSharedMemorySize,
                         (int)sizeof(GemmSmem));
    cudaFuncSetAttribute(k_attn, cudaFuncAttributeMaxDynamicSharedMemorySize,
                         (int)sizeof(AttnSmem));

    k_ln_tri<<<NP / 8, 256>>>(x, ln_w, ln_b, w_tri);
    k_proj<<<dim3(NP / 128, 4), 256, sizeof(GemmSmem)>>>(wq, wk, wv, wg);
    k_attn<<<dim3(N, H), 256, sizeof(AttnSmem)>>>(mask);
    k_out<<<NP / 128, 256, sizeof(GemmSmem)>>>(wo, bg, bo, out);
}

// round 8
// speedup vs baseline: 2.6845x; 1.0434x over previous
#include <cuda_runtime.h>
#include <math.h>
#include <stdint.h>

#define N 256
#define C 128
#define H 4
#define D 32
#define NP (N*N)            // 65536 positions
#define EPSV 1e-5f
#define INFV 1000000000.0f
#define QT 64               // attention query tile

// Scratch (static device arrays; no allocation in kernel_launch)
__device__ float g_xn[NP*C];        // layernormed x           32 MB
__device__ float g_tri[H*N*N];      // tri bias [h][q][k]       1 MB
__device__ float g_proj[4][NP*C];   // q, k, v, gate-logits   134 MB
__device__ float g_o[NP*C];         // attention output        32 MB

// round fp32 -> tf32 bit pattern (rna), returned as float bits
__device__ __forceinline__ float tf32r(float x) {
    uint32_t u;
    asm("cvt.rna.tf32.f32 %0, %1;" : "=r"(u) : "f"(x));
    return __uint_as_float(u);
}

__device__ __forceinline__ void mma_tf32(float& d0, float& d1, float& d2, float& d3,
                                         uint32_t a0, uint32_t a1, uint32_t a2, uint32_t a3,
                                         uint32_t b0, uint32_t b1) {
    asm volatile(
        "mma.sync.aligned.m16n8k8.row.col.f32.tf32.tf32.f32 "
        "{%0,%1,%2,%3}, {%4,%5,%6,%7}, {%8,%9}, {%0,%1,%2,%3};\n"
        : "+f"(d0), "+f"(d1), "+f"(d2), "+f"(d3)
        : "r"(a0), "r"(a1), "r"(a2), "r"(a3), "r"(b0), "r"(b1));
}

// ---------------------------------------------------------------------------
// Kernel 1: LayerNorm over C + triangle-bias projection ([h][q][k] layout)
// ---------------------------------------------------------------------------
__global__ void k_ln_tri(const float* __restrict__ x,
                         const float* __restrict__ ln_w,
                         const float* __restrict__ ln_b,
                         const float* __restrict__ w_tri) {
    __shared__ float swt[H*C];
    int tid = threadIdx.x;
    swt[tid]       = w_tri[tid];
    swt[tid + 256] = w_tri[tid + 256];
    __syncthreads();

    int warp = tid >> 5, lane = tid & 31;
    int pos = (blockIdx.x << 3) + warp;

    const float4 a = ((const float4*)(x + (size_t)pos * C))[lane];
    float s  = a.x + a.y + a.z + a.w;
    float s2 = a.x*a.x + a.y*a.y + a.z*a.z + a.w*a.w;
#pragma unroll
    for (int o = 16; o > 0; o >>= 1) {
        s  += __shfl_xor_sync(0xffffffffu, s,  o);
        s2 += __shfl_xor_sync(0xffffffffu, s2, o);
    }
    float mu   = s * (1.0f / C);
    float var  = s2 * (1.0f / C) - mu * mu;
    float rstd = rsqrtf(var + EPSV);

    float4 w = ((const float4*)ln_w)[lane];
    float4 b = ((const float4*)ln_b)[lane];
    float4 xn;
    xn.x = (a.x - mu) * rstd * w.x + b.x;
    xn.y = (a.y - mu) * rstd * w.y + b.y;
    xn.z = (a.z - mu) * rstd * w.z + b.z;
    xn.w = (a.w - mu) * rstd * w.w + b.w;
    ((float4*)(g_xn + (size_t)pos * C))[lane] = xn;

    float t[H];
#pragma unroll
    for (int h = 0; h < H; ++h) {
        const float4 wt = ((const float4*)(swt + h * C))[lane];
        t[h] = xn.x*wt.x + xn.y*wt.y + xn.z*wt.z + xn.w*wt.w;
    }
#pragma unroll
    for (int h = 0; h < H; ++h)
#pragma unroll
        for (int o = 16; o > 0; o >>= 1)
            t[h] += __shfl_xor_sync(0xffffffffu, t[h], o);

    if (lane == 0) {
        int q = pos >> 8, k = pos & 255;
#pragma unroll
        for (int h = 0; h < H; ++h)
            g_tri[(h * N + q) * N + k] = t[h];   // [h][q][k]
    }
}

struct MmaAcc { float d[2][8][4]; };   // [mt][nt][reg]

// M-side streamed chunk (pitch 36), N-side resident (pitch 132, cbase offset)
__device__ __forceinline__ void mma_chunk_mres(const float (*Ac)[36], const float (*Br)[132],
                                               int cbase, int wm, int wn, int g, int tq,
                                               MmaAcc& A) {
#pragma unroll
    for (int ks = 0; ks < 32; ks += 8) {
        uint32_t af[2][4];
#pragma unroll
        for (int mt = 0; mt < 2; ++mt) {
            int r = wm * 32 + mt * 16;
            af[mt][0] = __float_as_uint(Ac[r + g][ks + tq]);
            af[mt][1] = __float_as_uint(Ac[r + g + 8][ks + tq]);
            af[mt][2] = __float_as_uint(Ac[r + g][ks + tq + 4]);
            af[mt][3] = __float_as_uint(Ac[r + g + 8][ks + tq + 4]);
        }
#pragma unroll
        for (int nt = 0; nt < 8; ++nt) {
            int cb = wn * 64 + nt * 8;
            uint32_t b0 = __float_as_uint(Br[cb + g][cbase + ks + tq]);
            uint32_t b1 = __float_as_uint(Br[cb + g][cbase + ks + tq + 4]);
#pragma unroll
            for (int mt = 0; mt < 2; ++mt)
                mma_tf32(A.d[mt][nt][0], A.d[mt][nt][1], A.d[mt][nt][2], A.d[mt][nt][3],
                         af[mt][0], af[mt][1], af[mt][2], af[mt][3], b0, b1);
        }
    }
}

// M-side resident (pitch 132, cbase), N-side streamed chunk (pitch 36)
__device__ __forceinline__ void mma_chunk_nstr(const float (*Ar)[132], const float (*Bc)[36],
                                               int cbase, int wm, int wn, int g, int tq,
                                               MmaAcc& A) {
#pragma unroll
    for (int ks = 0; ks < 32; ks += 8) {
        uint32_t af[2][4];
#pragma unroll
        for (int mt = 0; mt < 2; ++mt) {
            int r = wm * 32 + mt * 16;
            af[mt][0] = __float_as_uint(Ar[r + g][cbase + ks + tq]);
            af[mt][1] = __float_as_uint(Ar[r + g + 8][cbase + ks + tq]);
            af[mt][2] = __float_as_uint(Ar[r + g][cbase + ks + tq + 4]);
            af[mt][3] = __float_as_uint(Ar[r + g + 8][cbase + ks + tq + 4]);
        }
#pragma unroll
        for (int nt = 0; nt < 8; ++nt) {
            int cb = wn * 64 + nt * 8;
            uint32_t b0 = __float_as_uint(Bc[cb + g][ks + tq]);
            uint32_t b1 = __float_as_uint(Bc[cb + g][ks + tq + 4]);
#pragma unroll
            for (int mt = 0; mt < 2; ++mt)
                mma_tf32(A.d[mt][nt][0], A.d[mt][nt][1], A.d[mt][nt][2], A.d[mt][nt][3],
                         af[mt][0], af[mt][1], af[mt][2], af[mt][3], b0, b1);
        }
    }
}

// ---------------------------------------------------------------------------
// Kernel 2: QKV + gate projections, fused. grid = NP/128.
// A (xn rows) resident; 4 weights stream through double-buffered 32-chunks.
// ---------------------------------------------------------------------------
struct ProjSmem {
    float As[128][132];     // resident xn tile   67584 B
    float Bs[2][128][36];   // weight chunks      36864 B
};                          // 104448 B

__global__ void __launch_bounds__(256, 2)
k_proj(const float* __restrict__ wq, const float* __restrict__ wk,
       const float* __restrict__ wv, const float* __restrict__ wg) {
    extern __shared__ char smraw[];
    ProjSmem* sm = (ProjSmem*)smraw;
    int tid = threadIdx.x;
    int m0 = blockIdx.x * 128;
    int w = tid >> 5, lane = tid & 31;
    int wm = w >> 1, wn = w & 1;
    int g = lane >> 2, tq = lane & 3;

    // stage resident A (xn rows, tf32-rounded)
#pragma unroll
    for (int t = 0; t < 16; ++t) {
        int idx = tid + t * 256;          // 0..4095
        int row = idx >> 5, j4 = idx & 31;
        float4 a = *(const float4*)&g_xn[(size_t)(m0 + row) * C + j4 * 4];
        float4 r = {tf32r(a.x), tf32r(a.y), tf32r(a.z), tf32r(a.w)};
        *(float4*)&sm->As[row][j4 * 4] = r;
    }
    // stage B chunk 0 (wq, cols 0..31)
#pragma unroll
    for (int t = 0; t < 4; ++t) {
        int idx = tid + t * 256;          // 0..1023
        int row = idx >> 3, j = idx & 7;
        float4 b = *(const float4*)&wq[(size_t)row * C + j * 4];
        float4 r = {tf32r(b.x), tf32r(b.y), tf32r(b.z), tf32r(b.w)};
        *(float4*)&sm->Bs[0][row][j * 4] = r;
    }
    __syncthreads();

    MmaAcc acc;
#pragma unroll
    for (int mt = 0; mt < 2; ++mt)
#pragma unroll
        for (int nt = 0; nt < 8; ++nt)
#pragma unroll
            for (int r = 0; r < 4; ++r) acc.d[mt][nt][r] = 0.0f;

    for (int s = 0; s < 16; ++s) {        // s = wsel*4 + kc
        int wsel = s >> 2, kc = s & 3;
        float4 pre[4];
        if (s < 15) {
            int ws2 = (s + 1) >> 2, kc2 = (s + 1) & 3;
            const float* Wn = (ws2 == 0) ? wq : (ws2 == 1) ? wk : (ws2 == 2) ? wv : wg;
#pragma unroll
            for (int t = 0; t < 4; ++t) {
                int idx = tid + t * 256;
                int row = idx >> 3, j = idx & 7;
                pre[t] = *(const float4*)&Wn[(size_t)row * C + kc2 * 32 + j * 4];
            }
        }
        mma_chunk_nstr(sm->As, sm->Bs[s & 1], kc * 32, wm, wn, g, tq, acc);
        if (s < 15) {
#pragma unroll
            for (int t = 0; t < 4; ++t) {
                int idx = tid + t * 256;
                int row = idx >> 3, j = idx & 7;
                float4 r = {tf32r(pre[t].x), tf32r(pre[t].y), tf32r(pre[t].z), tf32r(pre[t].w)};
                *(float4*)&sm->Bs[(s + 1) & 1][row][j * 4] = r;
            }
            __syncthreads();
        }
        if (kc == 3) {
            float* Out = g_proj[wsel];
#pragma unroll
            for (int mt = 0; mt < 2; ++mt) {
                int r0 = m0 + wm * 32 + mt * 16 + g;
#pragma unroll
                for (int nt = 0; nt < 8; ++nt) {
                    int cb = wn * 64 + nt * 8 + 2 * tq;
                    *(float2*)&Out[(size_t)r0 * C + cb] =
                        make_float2(acc.d[mt][nt][0], acc.d[mt][nt][1]);
                    *(float2*)&Out[(size_t)(r0 + 8) * C + cb] =
                        make_float2(acc.d[mt][nt][2], acc.d[mt][nt][3]);
                    acc.d[mt][nt][0] = acc.d[mt][nt][1] = 0.0f;
                    acc.d[mt][nt][2] = acc.d[mt][nt][3] = 0.0f;
                }
            }
        }
    }
}

// ---------------------------------------------------------------------------
// Kernel 3: MMA attention. Block = (i, h); loops 4 query tiles, K/V loaded once.
// ---------------------------------------------------------------------------
struct AttnSmem {
    float Ks[256][36];   // K tile, tf32-rounded          36864 B
    float Vs[256][36];   // V tile, tf32-rounded          36864 B
    float Qs[QT][36];    // Q tile, scaled + rounded       9216 B
    float T[QT][260];    // tri bias -> then P (rounded)  66560 B
    float mb[256];       // mask bias                      1024 B
    float rmax[QT][4];   // per-row partial max (by wn)    1024 B
    float rsum[QT][4];   // per-row partial sum (by wn)    1024 B
};                       // total 152576 B

__global__ void __launch_bounds__(256)
k_attn(const float* __restrict__ mask) {
    extern __shared__ char smraw[];
    AttnSmem* sm = (AttnSmem*)smraw;

    int i = blockIdx.x, h = blockIdx.y;
    int tid = threadIdx.x, w = tid >> 5, lane = tid & 31;
    int g = lane >> 2, tq = lane & 3;
    int wm = w >> 2, wn = w & 3;          // S: 2 warps along M(64), 4 along N(256)

    const float* Kg = g_proj[1] + (size_t)i * N * C + h * D;
    const float* Vg = g_proj[2] + (size_t)i * N * C + h * D;

    // ---- load K, V (row = tid), round to tf32; mask bias ----
#pragma unroll
    for (int j = 0; j < 8; ++j) {
        float4 kv = *(const float4*)&Kg[(size_t)tid * C + j * 4];
        sm->Ks[tid][j*4+0] = tf32r(kv.x); sm->Ks[tid][j*4+1] = tf32r(kv.y);
        sm->Ks[tid][j*4+2] = tf32r(kv.z); sm->Ks[tid][j*4+3] = tf32r(kv.w);
        float4 vv = *(const float4*)&Vg[(size_t)tid * C + j * 4];
        sm->Vs[tid][j*4+0] = tf32r(vv.x); sm->Vs[tid][j*4+1] = tf32r(vv.y);
        sm->Vs[tid][j*4+2] = tf32r(vv.z); sm->Vs[tid][j*4+3] = tf32r(vv.w);
    }
    sm->mb[tid] = INFV * (mask[i * N + tid] - 1.0f);

    for (int qt = 0; qt < 4; ++qt) {
        int q0 = qt * QT;
        __syncthreads();   // K/V/mb visible (iter 0); T/Qs/rsum free (iters > 0)

        const float* Qg = g_proj[0] + ((size_t)(i * N + q0)) * C + h * D;
        // ---- load Q tile (scaled by 1/sqrt(D)) ----
#pragma unroll
        for (int t = 0; t < 2; ++t) {
            int idx = tid + t * 256;           // 0..511
            int row = idx >> 3, j = idx & 7;
            float4 qv = *(const float4*)&Qg[(size_t)row * C + j * 4];
            const float sc = 0.17677669529663688f;
            sm->Qs[row][j*4+0] = tf32r(qv.x * sc); sm->Qs[row][j*4+1] = tf32r(qv.y * sc);
            sm->Qs[row][j*4+2] = tf32r(qv.z * sc); sm->Qs[row][j*4+3] = tf32r(qv.w * sc);
        }
        // ---- load tri tile [q0..q0+63][0..255] into T (fp32) ----
#pragma unroll
        for (int t = 0; t < 16; ++t) {
            int idx = tid + t * 256;           // 0..4095
            int row = idx >> 6, k4 = idx & 63;
            float4 tv = *(const float4*)&g_tri[((size_t)(h * N + q0 + row)) * N + k4 * 4];
            *(float4*)&sm->T[row][k4 * 4] = tv;
        }
        __syncthreads();

        // ---- S = Q K^T : warp tile 32x64, 2mt x 8nt, k=32 ----
        float sacc[2][8][4];
#pragma unroll
        for (int mt = 0; mt < 2; ++mt)
#pragma unroll
            for (int nt = 0; nt < 8; ++nt)
#pragma unroll
                for (int r = 0; r < 4; ++r) sacc[mt][nt][r] = 0.0f;

#pragma unroll
        for (int ks = 0; ks < 32; ks += 8) {
            uint32_t af[2][4];
#pragma unroll
            for (int mt = 0; mt < 2; ++mt) {
                int r = wm * 32 + mt * 16;
                af[mt][0] = __float_as_uint(sm->Qs[r + g][ks + tq]);
                af[mt][1] = __float_as_uint(sm->Qs[r + g + 8][ks + tq]);
                af[mt][2] = __float_as_uint(sm->Qs[r + g][ks + tq + 4]);
                af[mt][3] = __float_as_uint(sm->Qs[r + g + 8][ks + tq + 4]);
            }
#pragma unroll
            for (int nt = 0; nt < 8; ++nt) {
                int cb = wn * 64 + nt * 8;
                uint32_t b0 = __float_as_uint(sm->Ks[cb + g][ks + tq]);
                uint32_t b1 = __float_as_uint(sm->Ks[cb + g][ks + tq + 4]);
#pragma unroll
                for (int mt = 0; mt < 2; ++mt)
                    mma_tf32(sacc[mt][nt][0], sacc[mt][nt][1], sacc[mt][nt][2], sacc[mt][nt][3],
                             af[mt][0], af[mt][1], af[mt][2], af[mt][3], b0, b1);
            }
        }

        // ---- add tri + mask bias; partial row max ----
        float pmax[2][2];
        pmax[0][0] = pmax[0][1] = pmax[1][0] = pmax[1][1] = -3.4e38f;
#pragma unroll
        for (int mt = 0; mt < 2; ++mt) {
            int r0 = wm * 32 + mt * 16 + g;
#pragma unroll
            for (int nt = 0; nt < 8; ++nt) {
                int c0 = wn * 64 + nt * 8 + 2 * tq;
                float m0v = sm->mb[c0], m1v = sm->mb[c0 + 1];
                sacc[mt][nt][0] += sm->T[r0][c0]     + m0v;
                sacc[mt][nt][1] += sm->T[r0][c0 + 1] + m1v;
                sacc[mt][nt][2] += sm->T[r0 + 8][c0]     + m0v;
                sacc[mt][nt][3] += sm->T[r0 + 8][c0 + 1] + m1v;
                pmax[mt][0] = fmaxf(pmax[mt][0], fmaxf(sacc[mt][nt][0], sacc[mt][nt][1]));
                pmax[mt][1] = fmaxf(pmax[mt][1], fmaxf(sacc[mt][nt][2], sacc[mt][nt][3]));
            }
        }
#pragma unroll
        for (int mt = 0; mt < 2; ++mt)
#pragma unroll
            for (int rh = 0; rh < 2; ++rh) {
                float v = pmax[mt][rh];
                v = fmaxf(v, __shfl_xor_sync(0xffffffffu, v, 1));
                v = fmaxf(v, __shfl_xor_sync(0xffffffffu, v, 2));
                pmax[mt][rh] = v;
            }
        if (tq == 0) {
#pragma unroll
            for (int mt = 0; mt < 2; ++mt) {
                int r0 = wm * 32 + mt * 16 + g;
                sm->rmax[r0][wn]     = pmax[mt][0];
                sm->rmax[r0 + 8][wn] = pmax[mt][1];
            }
        }
        __syncthreads();

        // ---- exp + write P (tf32-rounded) + partial row sums ----
        float psum[2][2] = {{0.0f, 0.0f}, {0.0f, 0.0f}};
#pragma unroll
        for (int mt = 0; mt < 2; ++mt) {
            int r0 = wm * 32 + mt * 16 + g;
            float4 m4a = *(float4*)sm->rmax[r0];
            float rm0 = fmaxf(fmaxf(m4a.x, m4a.y), fmaxf(m4a.z, m4a.w));
            float4 m4b = *(float4*)sm->rmax[r0 + 8];
            float rm1 = fmaxf(fmaxf(m4b.x, m4b.y), fmaxf(m4b.z, m4b.w));
#pragma unroll
            for (int nt = 0; nt < 8; ++nt) {
                int c0 = wn * 64 + nt * 8 + 2 * tq;
                float p0 = tf32r(__expf(sacc[mt][nt][0] - rm0));
                float p1 = tf32r(__expf(sacc[mt][nt][1] - rm0));
                float p2 = tf32r(__expf(sacc[mt][nt][2] - rm1));
                float p3 = tf32r(__expf(sacc[mt][nt][3] - rm1));
                psum[mt][0] += p0 + p1;
                psum[mt][1] += p2 + p3;
                sm->T[r0][c0] = p0;     sm->T[r0][c0 + 1] = p1;
                sm->T[r0 + 8][c0] = p2; sm->T[r0 + 8][c0 + 1] = p3;
            }
        }
#pragma unroll
        for (int mt = 0; mt < 2; ++mt)
#pragma unroll
            for (int rh = 0; rh < 2; ++rh) {
                float v = psum[mt][rh];
                v += __shfl_xor_sync(0xffffffffu, v, 1);
                v += __shfl_xor_sync(0xffffffffu, v, 2);
                psum[mt][rh] = v;
            }
        if (tq == 0) {
#pragma unroll
            for (int mt = 0; mt < 2; ++mt) {
                int r0 = wm * 32 + mt * 16 + g;
                sm->rsum[r0][wn]     = psum[mt][0];
                sm->rsum[r0 + 8][wn] = psum[mt][1];
            }
        }
        __syncthreads();

        // ---- O = P V : warp tile 32x8, k=256 ----
        int nb = wn * 8;
        float oacc[2][4] = {{0,0,0,0},{0,0,0,0}};
#pragma unroll
        for (int ks8 = 0; ks8 < 32; ++ks8) {
            int kk = ks8 * 8;
            uint32_t b0 = __float_as_uint(sm->Vs[kk + tq][nb + g]);
            uint32_t b1 = __float_as_uint(sm->Vs[kk + tq + 4][nb + g]);
#pragma unroll
            for (int mt = 0; mt < 2; ++mt) {
                int r0 = wm * 32 + mt * 16 + g;
                uint32_t a0 = __float_as_uint(sm->T[r0][kk + tq]);
                uint32_t a1 = __float_as_uint(sm->T[r0 + 8][kk + tq]);
                uint32_t a2 = __float_as_uint(sm->T[r0][kk + tq + 4]);
                uint32_t a3 = __float_as_uint(sm->T[r0 + 8][kk + tq + 4]);
                mma_tf32(oacc[mt][0], oacc[mt][1], oacc[mt][2], oacc[mt][3],
                         a0, a1, a2, a3, b0, b1);
            }
        }

        // ---- epilogue: normalize by row sums, store ----
#pragma unroll
        for (int mt = 0; mt < 2; ++mt) {
            int r0 = wm * 32 + mt * 16 + g;
            float4 s0 = *(float4*)sm->rsum[r0];
            float inv0 = 1.0f / (s0.x + s0.y + s0.z + s0.w);
            float4 s1 = *(float4*)sm->rsum[r0 + 8];
            float inv1 = 1.0f / (s1.x + s1.y + s1.z + s1.w);
            int col = nb + 2 * tq;
            size_t b0a = ((size_t)(i * N + q0 + r0)) * C + h * D + col;
            *(float2*)&g_o[b0a] = make_float2(oacc[mt][0] * inv0, oacc[mt][1] * inv0);
            size_t b1a = ((size_t)(i * N + q0 + r0 + 8)) * C + h * D + col;
            *(float2*)&g_o[b1a] = make_float2(oacc[mt][2] * inv1, oacc[mt][3] * inv1);
        }
    }
}

// ---------------------------------------------------------------------------
// Kernel 4: gated output projection. grid=NP/128.
// B (wo) resident; A (gated o) streamed with register prefetch.
// ---------------------------------------------------------------------------
struct OutSmem {
    float Bs[128][132];     // resident wo        67584 B
    float As[2][128][36];   // gated A chunks     36864 B
};                          // 104448 B

__global__ void __launch_bounds__(256)
k_out(const float* __restrict__ wo, const float* __restrict__ bg,
      const float* __restrict__ bo, float* __restrict__ out) {
    extern __shared__ char smraw[];
    OutSmem* sm = (OutSmem*)smraw;
    int tid = threadIdx.x;
    int m0 = blockIdx.x * 128;
    int w = tid >> 5, lane = tid & 31;
    int wm = w >> 1, wn = w & 1;
    int g = lane >> 2, tq = lane & 3;

    // stage full B (wo, tf32-rounded)
#pragma unroll
    for (int t = 0; t < 16; ++t) {
        int idx = tid + t * 256;
        int row = idx >> 5, j4 = idx & 31;
        float4 b = *(const float4*)&wo[(size_t)row * C + j4 * 4];
        float4 r = {tf32r(b.x), tf32r(b.y), tf32r(b.z), tf32r(b.w)};
        *(float4*)&sm->Bs[row][j4 * 4] = r;
    }
    // stage A chunk 0 (gated)
#pragma unroll
    for (int t = 0; t < 4; ++t) {
        int idx = tid + t * 256;
        int row = idx >> 3, j = idx & 7;
        int col = j * 4;
        size_t ai = (size_t)(m0 + row) * C + col;
        float4 ov = *(const float4*)&g_o[ai];
        float4 gp = *(const float4*)&g_proj[3][ai];
        float4 bgv = *(const float4*)&bg[col];
        float4 r;
        r.x = tf32r(ov.x / (1.0f + __expf(-(gp.x + bgv.x))));
        r.y = tf32r(ov.y / (1.0f + __expf(-(gp.y + bgv.y))));
        r.z = tf32r(ov.z / (1.0f + __expf(-(gp.z + bgv.z))));
        r.w = tf32r(ov.w / (1.0f + __expf(-(gp.w + bgv.w))));
        *(float4*)&sm->As[0][row][j * 4] = r;
    }
    __syncthreads();

    MmaAcc acc;
#pragma unroll
    for (int mt = 0; mt < 2; ++mt)
#pragma unroll
        for (int nt = 0; nt < 8; ++nt)
#pragma unroll
            for (int r = 0; r < 4; ++r) acc.d[mt][nt][r] = 0.0f;

    for (int kc = 0; kc < 4; ++kc) {
        float4 po[4], pg[4];
        if (kc < 3) {
#pragma unroll
            for (int t = 0; t < 4; ++t) {
                int idx = tid + t * 256;
                int row = idx >> 3, j = idx & 7;
                size_t ai = (size_t)(m0 + row) * C + (kc + 1) * 32 + j * 4;
                po[t] = *(const float4*)&g_o[ai];
                pg[t] = *(const float4*)&g_proj[3][ai];
            }
        }
        mma_chunk_mres(sm->As[kc & 1], sm->Bs, kc * 32, wm, wn, g, tq, acc);
        if (kc < 3) {
#pragma unroll
            for (int t = 0; t < 4; ++t) {
                int idx = tid + t * 256;
                int row = idx >> 3, j = idx & 7;
                int col = (kc + 1) * 32 + j * 4;
                float4 bgv = *(const float4*)&bg[col];
                float4 r;
                r.x = tf32r(po[t].x / (1.0f + __expf(-(pg[t].x + bgv.x))));
                r.y = tf32r(po[t].y / (1.0f + __expf(-(pg[t].y + bgv.y))));
                r.z = tf32r(po[t].z / (1.0f + __expf(-(pg[t].z + bgv.z))));
                r.w = tf32r(po[t].w / (1.0f + __expf(-(pg[t].w + bgv.w))));
                *(float4*)&sm->As[(kc + 1) & 1][row][j * 4] = r;
            }
            __syncthreads();
        }
    }

#pragma unroll
    for (int mt = 0; mt < 2; ++mt) {
        int r0 = m0 + wm * 32 + mt * 16 + g;
#pragma unroll
        for (int nt = 0; nt < 8; ++nt) {
            int cb = wn * 64 + nt * 8 + 2 * tq;
            float2 bov = *(const float2*)&bo[cb];
            *(float2*)&out[(size_t)r0 * C + cb] =
                make_float2(acc.d[mt][nt][0] + bov.x, acc.d[mt][nt][1] + bov.y);
            *(float2*)&out[(size_t)(r0 + 8) * C + cb] =
                make_float2(acc.d[mt][nt][2] + bov.x, acc.d[mt][nt][3] + bov.y);
        }
    }
}

// ---------------------------------------------------------------------------
extern "C" void kernel_launch(void* const* d_in, const int* in_sizes, int n_in,
                              void* d_out, int out_size) {
    const float* x     = (const float*)d_in[0];
    const float* mask  = (const float*)d_in[1];
    const float* ln_w  = (const float*)d_in[2];
    const float* ln_b  = (const float*)d_in[3];
    const float* w_tri = (const float*)d_in[4];
    const float* wq    = (const float*)d_in[5];
    const float* wk    = (const float*)d_in[6];
    const float* wv    = (const float*)d_in[7];
    const float* wg    = (const float*)d_in[8];
    const float* bg    = (const float*)d_in[9];
    const float* wo    = (const float*)d_in[10];
    const float* bo    = (const float*)d_in[11];
    float* out = (float*)d_out;

    (void)in_sizes; (void)n_in; (void)out_size;

    cudaFuncSetAttribute(k_proj, cudaFuncAttributeMaxDynamicSharedMemorySize,
                         (int)sizeof(ProjSmem));
    cudaFuncSetAttribute(k_out, cudaFuncAttributeMaxDynamicSharedMemorySize,
                         (int)sizeof(OutSmem));
    cudaFuncSetAttribute(k_attn, cudaFuncAttributeMaxDynamicSharedMemorySize,
                         (int)sizeof(AttnSmem));

    k_ln_tri<<<NP / 8, 256>>>(x, ln_w, ln_b, w_tri);
    k_proj<<<NP / 128, 256, sizeof(ProjSmem)>>>(wq, wk, wv, wg);
    k_attn<<<dim3(N, H), 256, sizeof(AttnSmem)>>>(mask);
    k_out<<<NP / 128, 256, sizeof(OutSmem)>>>(wo, bg, bo, out);
}

// round 9
// speedup vs baseline: 3.0569x; 1.1387x over previous
#include <cuda_runtime.h>
#include <math.h>
#include <stdint.h>

#define N 256
#define C 128
#define H 4
#define D 32
#define NP (N*N)            // 65536 positions
#define EPSV 1e-5f
#define INFV 1000000000.0f
#define QT 64               // attention query tile

// Scratch (static device arrays; no allocation in kernel_launch)
__device__ float g_xn[NP*C];        // layernormed x           32 MB
__device__ float g_tri[H*N*N];      // tri bias [h][q][k]       1 MB
__device__ float g_gate[NP*C];      // gate logits             32 MB
__device__ float g_o[NP*C];         // attention output        32 MB

// round fp32 -> tf32 bit pattern (rna), returned as float bits
__device__ __forceinline__ float tf32r(float x) {
    uint32_t u;
    asm("cvt.rna.tf32.f32 %0, %1;" : "=r"(u) : "f"(x));
    return __uint_as_float(u);
}

__device__ __forceinline__ void mma_tf32(float& d0, float& d1, float& d2, float& d3,
                                         uint32_t a0, uint32_t a1, uint32_t a2, uint32_t a3,
                                         uint32_t b0, uint32_t b1) {
    asm volatile(
        "mma.sync.aligned.m16n8k8.row.col.f32.tf32.tf32.f32 "
        "{%0,%1,%2,%3}, {%4,%5,%6,%7}, {%8,%9}, {%0,%1,%2,%3};\n"
        : "+f"(d0), "+f"(d1), "+f"(d2), "+f"(d3)
        : "r"(a0), "r"(a1), "r"(a2), "r"(a3), "r"(b0), "r"(b1));
}

// ---------------------------------------------------------------------------
// Kernel 1: LayerNorm over C + triangle-bias projection ([h][q][k] layout)
// ---------------------------------------------------------------------------
__global__ void k_ln_tri(const float* __restrict__ x,
                         const float* __restrict__ ln_w,
                         const float* __restrict__ ln_b,
                         const float* __restrict__ w_tri) {
    __shared__ float swt[H*C];
    int tid = threadIdx.x;
    swt[tid]       = w_tri[tid];
    swt[tid + 256] = w_tri[tid + 256];
    __syncthreads();

    int warp = tid >> 5, lane = tid & 31;
    int pos = (blockIdx.x << 3) + warp;

    const float4 a = ((const float4*)(x + (size_t)pos * C))[lane];
    float s  = a.x + a.y + a.z + a.w;
    float s2 = a.x*a.x + a.y*a.y + a.z*a.z + a.w*a.w;
#pragma unroll
    for (int o = 16; o > 0; o >>= 1) {
        s  += __shfl_xor_sync(0xffffffffu, s,  o);
        s2 += __shfl_xor_sync(0xffffffffu, s2, o);
    }
    float mu   = s * (1.0f / C);
    float var  = s2 * (1.0f / C) - mu * mu;
    float rstd = rsqrtf(var + EPSV);

    float4 w = ((const float4*)ln_w)[lane];
    float4 b = ((const float4*)ln_b)[lane];
    float4 xn;
    xn.x = (a.x - mu) * rstd * w.x + b.x;
    xn.y = (a.y - mu) * rstd * w.y + b.y;
    xn.z = (a.z - mu) * rstd * w.z + b.z;
    xn.w = (a.w - mu) * rstd * w.w + b.w;
    ((float4*)(g_xn + (size_t)pos * C))[lane] = xn;

    float t[H];
#pragma unroll
    for (int h = 0; h < H; ++h) {
        const float4 wt = ((const float4*)(swt + h * C))[lane];
        t[h] = xn.x*wt.x + xn.y*wt.y + xn.z*wt.z + xn.w*wt.w;
    }
#pragma unroll
    for (int h = 0; h < H; ++h)
#pragma unroll
        for (int o = 16; o > 0; o >>= 1)
            t[h] += __shfl_xor_sync(0xffffffffu, t[h], o);

    if (lane == 0) {
        int q = pos >> 8, k = pos & 255;
#pragma unroll
        for (int h = 0; h < H; ++h)
            g_tri[(h * N + q) * N + k] = t[h];   // [h][q][k]
    }
}

struct MmaAcc { float d[2][8][4]; };   // [mt][nt][reg]

// M-side streamed chunk (pitch 36), N-side resident (pitch 132, cbase offset)
__device__ __forceinline__ void mma_chunk_mres(const float (*Ac)[36], const float (*Br)[132],
                                               int cbase, int wm, int wn, int g, int tq,
                                               MmaAcc& A) {
#pragma unroll
    for (int ks = 0; ks < 32; ks += 8) {
        uint32_t af[2][4];
#pragma unroll
        for (int mt = 0; mt < 2; ++mt) {
            int r = wm * 32 + mt * 16;
            af[mt][0] = __float_as_uint(Ac[r + g][ks + tq]);
            af[mt][1] = __float_as_uint(Ac[r + g + 8][ks + tq]);
            af[mt][2] = __float_as_uint(Ac[r + g][ks + tq + 4]);
            af[mt][3] = __float_as_uint(Ac[r + g + 8][ks + tq + 4]);
        }
#pragma unroll
        for (int nt = 0; nt < 8; ++nt) {
            int cb = wn * 64 + nt * 8;
            uint32_t b0 = __float_as_uint(Br[cb + g][cbase + ks + tq]);
            uint32_t b1 = __float_as_uint(Br[cb + g][cbase + ks + tq + 4]);
#pragma unroll
            for (int mt = 0; mt < 2; ++mt)
                mma_tf32(A.d[mt][nt][0], A.d[mt][nt][1], A.d[mt][nt][2], A.d[mt][nt][3],
                         af[mt][0], af[mt][1], af[mt][2], af[mt][3], b0, b1);
        }
    }
}

// M-side resident (pitch 132, cbase), N-side streamed chunk (pitch 36)
__device__ __forceinline__ void mma_chunk_nstr(const float (*Ar)[132], const float (*Bc)[36],
                                               int cbase, int wm, int wn, int g, int tq,
                                               MmaAcc& A) {
#pragma unroll
    for (int ks = 0; ks < 32; ks += 8) {
        uint32_t af[2][4];
#pragma unroll
        for (int mt = 0; mt < 2; ++mt) {
            int r = wm * 32 + mt * 16;
            af[mt][0] = __float_as_uint(Ar[r + g][cbase + ks + tq]);
            af[mt][1] = __float_as_uint(Ar[r + g + 8][cbase + ks + tq]);
            af[mt][2] = __float_as_uint(Ar[r + g][cbase + ks + tq + 4]);
            af[mt][3] = __float_as_uint(Ar[r + g + 8][cbase + ks + tq + 4]);
        }
#pragma unroll
        for (int nt = 0; nt < 8; ++nt) {
            int cb = wn * 64 + nt * 8;
            uint32_t b0 = __float_as_uint(Bc[cb + g][ks + tq]);
            uint32_t b1 = __float_as_uint(Bc[cb + g][ks + tq + 4]);
#pragma unroll
            for (int mt = 0; mt < 2; ++mt)
                mma_tf32(A.d[mt][nt][0], A.d[mt][nt][1], A.d[mt][nt][2], A.d[mt][nt][3],
                         af[mt][0], af[mt][1], af[mt][2], af[mt][3], b0, b1);
        }
    }
}

// ---------------------------------------------------------------------------
// Kernel 2: gate-logit projection only. grid = NP/128.
// A (xn rows) resident; wg streams through double-buffered 32-chunks.
// ---------------------------------------------------------------------------
struct ProjSmem {
    float As[128][132];     // resident xn tile   67584 B
    float Bs[2][128][36];   // weight chunks      36864 B
};                          // 104448 B

__global__ void __launch_bounds__(256, 2)
k_gate(const float* __restrict__ wg) {
    extern __shared__ char smraw[];
    ProjSmem* sm = (ProjSmem*)smraw;
    int tid = threadIdx.x;
    int m0 = blockIdx.x * 128;
    int w = tid >> 5, lane = tid & 31;
    int wm = w >> 1, wn = w & 1;
    int g = lane >> 2, tq = lane & 3;

    // stage resident A (xn rows, tf32-rounded)
#pragma unroll
    for (int t = 0; t < 16; ++t) {
        int idx = tid + t * 256;          // 0..4095
        int row = idx >> 5, j4 = idx & 31;
        float4 a = *(const float4*)&g_xn[(size_t)(m0 + row) * C + j4 * 4];
        float4 r = {tf32r(a.x), tf32r(a.y), tf32r(a.z), tf32r(a.w)};
        *(float4*)&sm->As[row][j4 * 4] = r;
    }
    // stage B chunk 0 (wg, cols 0..31)
#pragma unroll
    for (int t = 0; t < 4; ++t) {
        int idx = tid + t * 256;          // 0..1023
        int row = idx >> 3, j = idx & 7;
        float4 b = *(const float4*)&wg[(size_t)row * C + j * 4];
        float4 r = {tf32r(b.x), tf32r(b.y), tf32r(b.z), tf32r(b.w)};
        *(float4*)&sm->Bs[0][row][j * 4] = r;
    }
    __syncthreads();

    MmaAcc acc;
#pragma unroll
    for (int mt = 0; mt < 2; ++mt)
#pragma unroll
        for (int nt = 0; nt < 8; ++nt)
#pragma unroll
            for (int r = 0; r < 4; ++r) acc.d[mt][nt][r] = 0.0f;

    for (int kc = 0; kc < 4; ++kc) {
        float4 pre[4];
        if (kc < 3) {
#pragma unroll
            for (int t = 0; t < 4; ++t) {
                int idx = tid + t * 256;
                int row = idx >> 3, j = idx & 7;
                pre[t] = *(const float4*)&wg[(size_t)row * C + (kc + 1) * 32 + j * 4];
            }
        }
        mma_chunk_nstr(sm->As, sm->Bs[kc & 1], kc * 32, wm, wn, g, tq, acc);
        if (kc < 3) {
#pragma unroll
            for (int t = 0; t < 4; ++t) {
                int idx = tid + t * 256;
                int row = idx >> 3, j = idx & 7;
                float4 r = {tf32r(pre[t].x), tf32r(pre[t].y), tf32r(pre[t].z), tf32r(pre[t].w)};
                *(float4*)&sm->Bs[(kc + 1) & 1][row][j * 4] = r;
            }
            __syncthreads();
        }
    }

#pragma unroll
    for (int mt = 0; mt < 2; ++mt) {
        int r0 = m0 + wm * 32 + mt * 16 + g;
#pragma unroll
        for (int nt = 0; nt < 8; ++nt) {
            int cb = wn * 64 + nt * 8 + 2 * tq;
            *(float2*)&g_gate[(size_t)r0 * C + cb] =
                make_float2(acc.d[mt][nt][0], acc.d[mt][nt][1]);
            *(float2*)&g_gate[(size_t)(r0 + 8) * C + cb] =
                make_float2(acc.d[mt][nt][2], acc.d[mt][nt][3]);
        }
    }
}

// ---------------------------------------------------------------------------
// Kernel 3: fused projection + MMA attention. Block = (i, h).
// Phase 1: K/V/Q = xn[i] x {Wk,Wv,Wq}_h via MMA, results kept in smem.
// Phase 2: per 64-query tile: S = Q K^T + tri + mask; softmax; O = P V.
// ---------------------------------------------------------------------------
struct AttnSmem {
    union {
        struct {
            float W3[96][132];   // stacked [k|v|q] head weights  50688 B
            float Xs[64][132];   // xn chunk                      33792 B
        } p;
        float T[QT][260];        // tri bias -> P                 66560 B
    } u;                         // 84480 B
    float Ks[256][36];           // 36864 B
    float Vs[256][36];           // 36864 B
    float Qs[256][36];           // 36864 B (pre-scaled)
    float mb[256];               //  1024 B
    float rmax[QT][4];           //  1024 B
    float rsum[QT][4];           //  1024 B
};                               // 198144 B

__global__ void __launch_bounds__(256)
k_attn(const float* __restrict__ mask,
       const float* __restrict__ wq, const float* __restrict__ wk,
       const float* __restrict__ wv) {
    extern __shared__ char smraw[];
    AttnSmem* sm = (AttnSmem*)smraw;

    int i = blockIdx.x, h = blockIdx.y;
    int tid = threadIdx.x, w = tid >> 5, lane = tid & 31;
    int g = lane >> 2, tq = lane & 3;
    int wm = w >> 2, wn = w & 3;          // 2 warps along M, 4 along N
    const float sc = 0.17677669529663688f;  // 1/sqrt(32)

    // ===================== Phase 1: project K/V/Q =====================
    // load head weights stacked: rows 0-31 = Wk_h, 32-63 = Wv_h, 64-95 = Wq_h
#pragma unroll
    for (int t = 0; t < 12; ++t) {
        int idx = tid + t * 256;          // 0..3071
        int row = idx >> 5, j4 = idx & 31;
        const float* src = (row < 32) ? wk : (row < 64) ? wv : wq;
        float4 b = *(const float4*)&src[(size_t)(h * 32 + (row & 31)) * C + j4 * 4];
        float4 r = {tf32r(b.x), tf32r(b.y), tf32r(b.z), tf32r(b.w)};
        *(float4*)&sm->u.p.W3[row][j4 * 4] = r;
    }
    sm->mb[tid] = INFV * (mask[i * N + tid] - 1.0f);

    for (int c = 0; c < 4; ++c) {
        __syncthreads();
        // stage xn rows [c*64, c*64+64)
#pragma unroll
        for (int t = 0; t < 8; ++t) {
            int idx = tid + t * 256;      // 0..2047
            int row = idx >> 5, j4 = idx & 31;
            float4 a = *(const float4*)&g_xn[((size_t)(i * N + c * 64 + row)) * C + j4 * 4];
            float4 r = {tf32r(a.x), tf32r(a.y), tf32r(a.z), tf32r(a.w)};
            *(float4*)&sm->u.p.Xs[row][j4 * 4] = r;
        }
        __syncthreads();

        // GEMM: M=64 (xn rows), N=96 (kvq dims), K=128
        float pacc[2][3][4] = {};
#pragma unroll
        for (int ks = 0; ks < 128; ks += 8) {
            uint32_t af[2][4];
#pragma unroll
            for (int mt = 0; mt < 2; ++mt) {
                int r = wm * 32 + mt * 16;
                af[mt][0] = __float_as_uint(sm->u.p.Xs[r + g][ks + tq]);
                af[mt][1] = __float_as_uint(sm->u.p.Xs[r + g + 8][ks + tq]);
                af[mt][2] = __float_as_uint(sm->u.p.Xs[r + g][ks + tq + 4]);
                af[mt][3] = __float_as_uint(sm->u.p.Xs[r + g + 8][ks + tq + 4]);
            }
#pragma unroll
            for (int nt = 0; nt < 3; ++nt) {
                int cb = wn * 24 + nt * 8;
                uint32_t b0 = __float_as_uint(sm->u.p.W3[cb + g][ks + tq]);
                uint32_t b1 = __float_as_uint(sm->u.p.W3[cb + g][ks + tq + 4]);
#pragma unroll
                for (int mt = 0; mt < 2; ++mt)
                    mma_tf32(pacc[mt][nt][0], pacc[mt][nt][1], pacc[mt][nt][2], pacc[mt][nt][3],
                             af[mt][0], af[mt][1], af[mt][2], af[mt][3], b0, b1);
            }
        }
        // scatter results into Ks / Vs / Qs (Q pre-scaled)
#pragma unroll
        for (int mt = 0; mt < 2; ++mt) {
            int row0 = c * 64 + wm * 32 + mt * 16 + g;
#pragma unroll
            for (int nt = 0; nt < 3; ++nt) {
                int col = wn * 24 + nt * 8 + 2 * tq;
                int sel = col >> 5, off = col & 31;
                float m0 = pacc[mt][nt][0], m1 = pacc[mt][nt][1];
                float m2 = pacc[mt][nt][2], m3 = pacc[mt][nt][3];
                if (sel == 2) { m0 *= sc; m1 *= sc; m2 *= sc; m3 *= sc; }
                float* dst = (sel == 0) ? &sm->Ks[0][0] :
                             (sel == 1) ? &sm->Vs[0][0] : &sm->Qs[0][0];
                dst[row0 * 36 + off]           = tf32r(m0);
                dst[row0 * 36 + off + 1]       = tf32r(m1);
                dst[(row0 + 8) * 36 + off]     = tf32r(m2);
                dst[(row0 + 8) * 36 + off + 1] = tf32r(m3);
            }
        }
    }

    // ===================== Phase 2: attention =====================
    for (int qt = 0; qt < 4; ++qt) {
        int q0 = qt * QT;
        __syncthreads();   // phase1/previous-qt done; T region free

        // ---- load tri tile [q0..q0+63][0..255] into T (fp32) ----
#pragma unroll
        for (int t = 0; t < 16; ++t) {
            int idx = tid + t * 256;           // 0..4095
            int row = idx >> 6, k4 = idx & 63;
            float4 tv = *(const float4*)&g_tri[((size_t)(h * N + q0 + row)) * N + k4 * 4];
            *(float4*)&sm->u.T[row][k4 * 4] = tv;
        }
        __syncthreads();

        // ---- S = Q K^T : warp tile 32x64, 2mt x 8nt, k=32 ----
        float sacc[2][8][4];
#pragma unroll
        for (int mt = 0; mt < 2; ++mt)
#pragma unroll
            for (int nt = 0; nt < 8; ++nt)
#pragma unroll
                for (int r = 0; r < 4; ++r) sacc[mt][nt][r] = 0.0f;

#pragma unroll
        for (int ks = 0; ks < 32; ks += 8) {
            uint32_t af[2][4];
#pragma unroll
            for (int mt = 0; mt < 2; ++mt) {
                int r = q0 + wm * 32 + mt * 16;
                af[mt][0] = __float_as_uint(sm->Qs[r + g][ks + tq]);
                af[mt][1] = __float_as_uint(sm->Qs[r + g + 8][ks + tq]);
                af[mt][2] = __float_as_uint(sm->Qs[r + g][ks + tq + 4]);
                af[mt][3] = __float_as_uint(sm->Qs[r + g + 8][ks + tq + 4]);
            }
#pragma unroll
            for (int nt = 0; nt < 8; ++nt) {
                int cb = wn * 64 + nt * 8;
                uint32_t b0 = __float_as_uint(sm->Ks[cb + g][ks + tq]);
                uint32_t b1 = __float_as_uint(sm->Ks[cb + g][ks + tq + 4]);
#pragma unroll
                for (int mt = 0; mt < 2; ++mt)
                    mma_tf32(sacc[mt][nt][0], sacc[mt][nt][1], sacc[mt][nt][2], sacc[mt][nt][3],
                             af[mt][0], af[mt][1], af[mt][2], af[mt][3], b0, b1);
            }
        }

        // ---- add tri + mask bias; partial row max ----
        float pmax[2][2];
        pmax[0][0] = pmax[0][1] = pmax[1][0] = pmax[1][1] = -3.4e38f;
#pragma unroll
        for (int mt = 0; mt < 2; ++mt) {
            int r0 = wm * 32 + mt * 16 + g;
#pragma unroll
            for (int nt = 0; nt < 8; ++nt) {
                int c0 = wn * 64 + nt * 8 + 2 * tq;
                float m0v = sm->mb[c0], m1v = sm->mb[c0 + 1];
                sacc[mt][nt][0] += sm->u.T[r0][c0]     + m0v;
                sacc[mt][nt][1] += sm->u.T[r0][c0 + 1] + m1v;
                sacc[mt][nt][2] += sm->u.T[r0 + 8][c0]     + m0v;
                sacc[mt][nt][3] += sm->u.T[r0 + 8][c0 + 1] + m1v;
                pmax[mt][0] = fmaxf(pmax[mt][0], fmaxf(sacc[mt][nt][0], sacc[mt][nt][1]));
                pmax[mt][1] = fmaxf(pmax[mt][1], fmaxf(sacc[mt][nt][2], sacc[mt][nt][3]));
            }
        }
#pragma unroll
        for (int mt = 0; mt < 2; ++mt)
#pragma unroll
            for (int rh = 0; rh < 2; ++rh) {
                float v = pmax[mt][rh];
                v = fmaxf(v, __shfl_xor_sync(0xffffffffu, v, 1));
                v = fmaxf(v, __shfl_xor_sync(0xffffffffu, v, 2));
                pmax[mt][rh] = v;
            }
        if (tq == 0) {
#pragma unroll
            for (int mt = 0; mt < 2; ++mt) {
                int r0 = wm * 32 + mt * 16 + g;
                sm->rmax[r0][wn]     = pmax[mt][0];
                sm->rmax[r0 + 8][wn] = pmax[mt][1];
            }
        }
        __syncthreads();

        // ---- exp + write P (tf32-rounded) + partial row sums ----
        float psum[2][2] = {{0.0f, 0.0f}, {0.0f, 0.0f}};
#pragma unroll
        for (int mt = 0; mt < 2; ++mt) {
            int r0 = wm * 32 + mt * 16 + g;
            float4 m4a = *(float4*)sm->rmax[r0];
            float rm0 = fmaxf(fmaxf(m4a.x, m4a.y), fmaxf(m4a.z, m4a.w));
            float4 m4b = *(float4*)sm->rmax[r0 + 8];
            float rm1 = fmaxf(fmaxf(m4b.x, m4b.y), fmaxf(m4b.z, m4b.w));
#pragma unroll
            for (int nt = 0; nt < 8; ++nt) {
                int c0 = wn * 64 + nt * 8 + 2 * tq;
                float p0 = tf32r(__expf(sacc[mt][nt][0] - rm0));
                float p1 = tf32r(__expf(sacc[mt][nt][1] - rm0));
                float p2 = tf32r(__expf(sacc[mt][nt][2] - rm1));
                float p3 = tf32r(__expf(sacc[mt][nt][3] - rm1));
                psum[mt][0] += p0 + p1;
                psum[mt][1] += p2 + p3;
                sm->u.T[r0][c0] = p0;     sm->u.T[r0][c0 + 1] = p1;
                sm->u.T[r0 + 8][c0] = p2; sm->u.T[r0 + 8][c0 + 1] = p3;
            }
        }
#pragma unroll
        for (int mt = 0; mt < 2; ++mt)
#pragma unroll
            for (int rh = 0; rh < 2; ++rh) {
                float v = psum[mt][rh];
                v += __shfl_xor_sync(0xffffffffu, v, 1);
                v += __shfl_xor_sync(0xffffffffu, v, 2);
                psum[mt][rh] = v;
            }
        if (tq == 0) {
#pragma unroll
            for (int mt = 0; mt < 2; ++mt) {
                int r0 = wm * 32 + mt * 16 + g;
                sm->rsum[r0][wn]     = psum[mt][0];
                sm->rsum[r0 + 8][wn] = psum[mt][1];
            }
        }
        __syncthreads();

        // ---- O = P V : warp tile 32x8, k=256 ----
        int nb = wn * 8;
        float oacc[2][4] = {{0,0,0,0},{0,0,0,0}};
#pragma unroll
        for (int ks8 = 0; ks8 < 32; ++ks8) {
            int kk = ks8 * 8;
            uint32_t b0 = __float_as_uint(sm->Vs[kk + tq][nb + g]);
            uint32_t b1 = __float_as_uint(sm->Vs[kk + tq + 4][nb + g]);
#pragma unroll
            for (int mt = 0; mt < 2; ++mt) {
                int r0 = wm * 32 + mt * 16 + g;
                uint32_t a0 = __float_as_uint(sm->u.T[r0][kk + tq]);
                uint32_t a1 = __float_as_uint(sm->u.T[r0 + 8][kk + tq]);
                uint32_t a2 = __float_as_uint(sm->u.T[r0][kk + tq + 4]);
                uint32_t a3 = __float_as_uint(sm->u.T[r0 + 8][kk + tq + 4]);
                mma_tf32(oacc[mt][0], oacc[mt][1], oacc[mt][2], oacc[mt][3],
                         a0, a1, a2, a3, b0, b1);
            }
        }

        // ---- epilogue: normalize by row sums, store ----
#pragma unroll
        for (int mt = 0; mt < 2; ++mt) {
            int r0 = wm * 32 + mt * 16 + g;
            float4 s0 = *(float4*)sm->rsum[r0];
            float inv0 = 1.0f / (s0.x + s0.y + s0.z + s0.w);
            float4 s1 = *(float4*)sm->rsum[r0 + 8];
            float inv1 = 1.0f / (s1.x + s1.y + s1.z + s1.w);
            int col = nb + 2 * tq;
            size_t b0a = ((size_t)(i * N + q0 + r0)) * C + h * D + col;
            *(float2*)&g_o[b0a] = make_float2(oacc[mt][0] * inv0, oacc[mt][1] * inv0);
            size_t b1a = ((size_t)(i * N + q0 + r0 + 8)) * C + h * D + col;
            *(float2*)&g_o[b1a] = make_float2(oacc[mt][2] * inv1, oacc[mt][3] * inv1);
        }
    }
}

// ---------------------------------------------------------------------------
// Kernel 4: gated output projection. grid=NP/128.
// B (wo) resident; A (gated o) streamed with register prefetch.
// ---------------------------------------------------------------------------
struct OutSmem {
    float Bs[128][132];     // resident wo        67584 B
    float As[2][128][36];   // gated A chunks     36864 B
};                          // 104448 B

__global__ void __launch_bounds__(256)
k_out(const float* __restrict__ wo, const float* __restrict__ bg,
      const float* __restrict__ bo, float* __restrict__ out) {
    extern __shared__ char smraw[];
    OutSmem* sm = (OutSmem*)smraw;
    int tid = threadIdx.x;
    int m0 = blockIdx.x * 128;
    int w = tid >> 5, lane = tid & 31;
    int wm = w >> 1, wn = w & 1;
    int g = lane >> 2, tq = lane & 3;

    // stage full B (wo, tf32-rounded)
#pragma unroll
    for (int t = 0; t < 16; ++t) {
        int idx = tid + t * 256;
        int row = idx >> 5, j4 = idx & 31;
        float4 b = *(const float4*)&wo[(size_t)row * C + j4 * 4];
        float4 r = {tf32r(b.x), tf32r(b.y), tf32r(b.z), tf32r(b.w)};
        *(float4*)&sm->Bs[row][j4 * 4] = r;
    }
    // stage A chunk 0 (gated)
#pragma unroll
    for (int t = 0; t < 4; ++t) {
        int idx = tid + t * 256;
        int row = idx >> 3, j = idx & 7;
        int col = j * 4;
        size_t ai = (size_t)(m0 + row) * C + col;
        float4 ov = *(const float4*)&g_o[ai];
        float4 gp = *(const float4*)&g_gate[ai];
        float4 bgv = *(const float4*)&bg[col];
        float4 r;
        r.x = tf32r(ov.x / (1.0f + __expf(-(gp.x + bgv.x))));
        r.y = tf32r(ov.y / (1.0f + __expf(-(gp.y + bgv.y))));
        r.z = tf32r(ov.z / (1.0f + __expf(-(gp.z + bgv.z))));
        r.w = tf32r(ov.w / (1.0f + __expf(-(gp.w + bgv.w))));
        *(float4*)&sm->As[0][row][j * 4] = r;
    }
    __syncthreads();

    MmaAcc acc;
#pragma unroll
    for (int mt = 0; mt < 2; ++mt)
#pragma unroll
        for (int nt = 0; nt < 8; ++nt)
#pragma unroll
            for (int r = 0; r < 4; ++r) acc.d[mt][nt][r] = 0.0f;

    for (int kc = 0; kc < 4; ++kc) {
        float4 po[4], pg[4];
        if (kc < 3) {
#pragma unroll
            for (int t = 0; t < 4; ++t) {
                int idx = tid + t * 256;
                int row = idx >> 3, j = idx & 7;
                size_t ai = (size_t)(m0 + row) * C + (kc + 1) * 32 + j * 4;
                po[t] = *(const float4*)&g_o[ai];
                pg[t] = *(const float4*)&g_gate[ai];
            }
        }
        mma_chunk_mres(sm->As[kc & 1], sm->Bs, kc * 32, wm, wn, g, tq, acc);
        if (kc < 3) {
#pragma unroll
            for (int t = 0; t < 4; ++t) {
                int idx = tid + t * 256;
                int row = idx >> 3, j = idx & 7;
                int col = (kc + 1) * 32 + j * 4;
                float4 bgv = *(const float4*)&bg[col];
                float4 r;
                r.x = tf32r(po[t].x / (1.0f + __expf(-(pg[t].x + bgv.x))));
                r.y = tf32r(po[t].y / (1.0f + __expf(-(pg[t].y + bgv.y))));
                r.z = tf32r(po[t].z / (1.0f + __expf(-(pg[t].z + bgv.z))));
                r.w = tf32r(po[t].w / (1.0f + __expf(-(pg[t].w + bgv.w))));
                *(float4*)&sm->As[(kc + 1) & 1][row][j * 4] = r;
            }
            __syncthreads();
        }
    }

#pragma unroll
    for (int mt = 0; mt < 2; ++mt) {
        int r0 = m0 + wm * 32 + mt * 16 + g;
#pragma unroll
        for (int nt = 0; nt < 8; ++nt) {
            int cb = wn * 64 + nt * 8 + 2 * tq;
            float2 bov = *(const float2*)&bo[cb];
            *(float2*)&out[(size_t)r0 * C + cb] =
                make_float2(acc.d[mt][nt][0] + bov.x, acc.d[mt][nt][1] + bov.y);
            *(float2*)&out[(size_t)(r0 + 8) * C + cb] =
                make_float2(acc.d[mt][nt][2] + bov.x, acc.d[mt][nt][3] + bov.y);
        }
    }
}

// ---------------------------------------------------------------------------
extern "C" void kernel_launch(void* const* d_in, const int* in_sizes, int n_in,
                              void* d_out, int out_size) {
    const float* x     = (const float*)d_in[0];
    const float* mask  = (const float*)d_in[1];
    const float* ln_w  = (const float*)d_in[2];
    const float* ln_b  = (const float*)d_in[3];
    const float* w_tri = (const float*)d_in[4];
    const float* wq    = (const float*)d_in[5];
    const float* wk    = (const float*)d_in[6];
    const float* wv    = (const float*)d_in[7];
    const float* wg    = (const float*)d_in[8];
    const float* bg    = (const float*)d_in[9];
    const float* wo    = (const float*)d_in[10];
    const float* bo    = (const float*)d_in[11];
    float* out = (float*)d_out;

    (void)in_sizes; (void)n_in; (void)out_size;

    cudaFuncSetAttribute(k_gate, cudaFuncAttributeMaxDynamicSharedMemorySize,
                         (int)sizeof(ProjSmem));
    cudaFuncSetAttribute(k_out, cudaFuncAttributeMaxDynamicSharedMemorySize,
                         (int)sizeof(OutSmem));
    cudaFuncSetAttribute(k_attn, cudaFuncAttributeMaxDynamicSharedMemorySize,
                         (int)sizeof(AttnSmem));

    k_ln_tri<<<NP / 8, 256>>>(x, ln_w, ln_b, w_tri);
    k_gate<<<NP / 128, 256, sizeof(ProjSmem)>>>(wg);
    k_attn<<<dim3(N, H), 256, sizeof(AttnSmem)>>>(mask, wq, wk, wv);
    k_out<<<NP / 128, 256, sizeof(OutSmem)>>>(wo, bg, bo, out);
}